// round 2
// baseline (speedup 1.0000x reference)
#include <cuda_runtime.h>

#define B_ 2
#define L_ 1024
#define D_ 1024
#define H_ 16
#define DH 64

// ---------------- scratch (no cudaMalloc allowed) ----------------
__device__ float g_q[B_*H_*L_*DH];      // 8 MB, head layout [b][h][i][d]
__device__ float g_k[B_*H_*L_*DH];
__device__ float g_v[B_*H_*L_*DH];
__device__ float g_Qr[H_*L_*DH];        // 4 MB, [h][m][d]
__device__ float g_O[B_*H_*L_*DH];      // attention output, head layout
__device__ float g_res[B_*L_*D_];       // residual before LN

// =================================================================
// Projection GEMM: C = A @ W, scatter to head layout.
// BM=BN=128, BK=16, 256 threads, 8x8 microtile.
// grid (8, 16, 4): z = 0:q(E,Wq) 1:k(Ev,Wke) 2:v(Ev,Wv) 3:Qr(R,Wkr)
// =================================================================
__global__ __launch_bounds__(256, 2)
void proj_gemm_kernel(const float* __restrict__ E,
                      const float* __restrict__ Ev,
                      const float* __restrict__ R,
                      const float* __restrict__ Wq,
                      const float* __restrict__ Wke,
                      const float* __restrict__ Wkr,
                      const float* __restrict__ Wv) {
    int which = blockIdx.z;
    const float* A; const float* W; float* out;
    if (which == 0)      { A = E;  W = Wq;  out = g_q;  }
    else if (which == 1) { A = Ev; W = Wke; out = g_k;  }
    else if (which == 2) { A = Ev; W = Wv;  out = g_v;  }
    else                 { A = R;  W = Wkr; out = g_Qr; if (blockIdx.y >= 8) return; }

    __shared__ float As[16][132];   // [k][i] transposed
    __shared__ float Bs[16][128];   // [k][j]

    int tid = threadIdx.x;
    int ty = tid >> 4, tx = tid & 15;
    int row0 = blockIdx.y * 128, col0 = blockIdx.x * 128;

    float acc[8][8];
#pragma unroll
    for (int i = 0; i < 8; i++)
#pragma unroll
        for (int j = 0; j < 8; j++) acc[i][j] = 0.f;

    for (int k0 = 0; k0 < D_; k0 += 16) {
#pragma unroll
        for (int l = 0; l < 2; l++) {
            int idx = tid + 256 * l;                   // 0..511
            int i = idx >> 2, c = (idx & 3) << 2;      // A: 128 rows x 16 k
            float4 av = *(const float4*)(A + (size_t)(row0 + i) * D_ + k0 + c);
            As[c + 0][i] = av.x; As[c + 1][i] = av.y;
            As[c + 2][i] = av.z; As[c + 3][i] = av.w;
            int kk = idx >> 5, cc = (idx & 31) << 2;   // B: 16 k x 128 cols
            *(float4*)&Bs[kk][cc] = *(const float4*)(W + (size_t)(k0 + kk) * D_ + col0 + cc);
        }
        __syncthreads();
#pragma unroll
        for (int kk = 0; kk < 16; kk++) {
            float a[8], bv[8];
            *(float4*)(a)     = *(const float4*)&As[kk][ty * 8];
            *(float4*)(a + 4) = *(const float4*)&As[kk][ty * 8 + 4];
            *(float4*)(bv)     = *(const float4*)&Bs[kk][tx * 8];
            *(float4*)(bv + 4) = *(const float4*)&Bs[kk][tx * 8 + 4];
#pragma unroll
            for (int ii = 0; ii < 8; ii++)
#pragma unroll
                for (int jj = 0; jj < 8; jj++)
                    acc[ii][jj] += a[ii] * bv[jj];
        }
        __syncthreads();
    }

    // scatter: row r -> (b, i), col c -> (h, d)
#pragma unroll
    for (int ii = 0; ii < 8; ii++) {
        int r = row0 + ty * 8 + ii;
        int bb = r >> 10, irow = r & 1023;
#pragma unroll
        for (int jj = 0; jj < 8; jj += 4) {
            int c = col0 + tx * 8 + jj;
            int hh = c >> 6, d = c & 63;
            float4 ov = make_float4(acc[ii][jj], acc[ii][jj + 1],
                                    acc[ii][jj + 2], acc[ii][jj + 3]);
            size_t off = (which == 3)
                ? ((size_t)(hh * L_ + irow)) * DH + d
                : ((size_t)((bb * H_ + hh) * L_ + irow)) * DH + d;
            *(float4*)(out + off) = ov;
        }
    }
}

// =================================================================
// Fused relative attention with online softmax.
// S[i,j] = (q_i+cb)·k_j + (q_i+pb)·Qr[L-1-i+j]  (Qr rows >= L are zero,
// which exactly implements the tril on the position terms; content terms
// are NOT masked, matching the reference).
// Block: 64 query rows of one (b,h). 256 threads, 4x4 microtiles.
// =================================================================
struct AttnSmem {
    float qcT[64][68];    // [d][i], q + cb
    float kT [64][68];    // [d][j]
    float vs [64][68];    // [j][d]
    float QrT[64][132];   // [d][t], t = j - i + 63 in [0,126]
    float Ps [64][68];    // [i][j]
    float deltas[64];     // pb - cb per d (qp = qc + delta)
    float red[64][17];
    float row_m[64], row_l[64], row_scale[64];
};

__global__ __launch_bounds__(256, 2)
void attn_kernel(const float* __restrict__ cb, const float* __restrict__ pb) {
    extern __shared__ float smem_raw[];
    AttnSmem& S = *reinterpret_cast<AttnSmem*>(smem_raw);

    int tid = threadIdx.x;
    int ty = tid >> 4, tx = tid & 15;
    int ty4 = ty * 4, tx4 = tx * 4;
    int ib = blockIdx.x;             // 0..15
    int bh = blockIdx.y;             // 0..31
    int h = bh & 15;
    int i0 = ib * 64;

    const float* qptr  = g_q  + (size_t)bh * L_ * DH;
    const float* kptr  = g_k  + (size_t)bh * L_ * DH;
    const float* vptr  = g_v  + (size_t)bh * L_ * DH;
    const float* Qrptr = g_Qr + (size_t)h  * L_ * DH;

    if (tid < 64) {
        S.row_m[tid] = -1e30f;
        S.row_l[tid] = 0.f;
        S.deltas[tid] = pb[h * DH + tid] - cb[h * DH + tid];
    }
    // load qcT = (q + cb) transposed  (lane-major-i store: conflict-free STS)
#pragma unroll
    for (int l = 0; l < 4; l++) {
        int idx = tid + 256 * l;          // 0..1023
        int i = idx & 63;
        int c = (idx >> 6) << 2;
        float4 qv = *(const float4*)(qptr + (size_t)(i0 + i) * DH + c);
        S.qcT[c + 0][i] = qv.x + cb[h * DH + c + 0];
        S.qcT[c + 1][i] = qv.y + cb[h * DH + c + 1];
        S.qcT[c + 2][i] = qv.z + cb[h * DH + c + 2];
        S.qcT[c + 3][i] = qv.w + cb[h * DH + c + 3];
    }

    float o[4][4];
#pragma unroll
    for (int a = 0; a < 4; a++)
#pragma unroll
        for (int b2 = 0; b2 < 4; b2++) o[a][b2] = 0.f;

    const int t0 = tx4 - ty4 + 63;

    for (int jt = 0; jt < 16; jt++) {
        int j0 = jt * 64;
        bool pos = (j0 <= i0);

        // ---- load k (transposed) and v tiles ----
#pragma unroll
        for (int l = 0; l < 4; l++) {
            int idx = tid + 256 * l;
            int i = idx & 63;
            int c = (idx >> 6) << 2;
            float4 kv = *(const float4*)(kptr + (size_t)(j0 + i) * DH + c);
            S.kT[c + 0][i] = kv.x; S.kT[c + 1][i] = kv.y;
            S.kT[c + 2][i] = kv.z; S.kT[c + 3][i] = kv.w;
            float4 vv = *(const float4*)(vptr + (size_t)(j0 + i) * DH + c);
            *(float4*)&S.vs[i][c] = vv;
        }
        // ---- load Qr band (transposed), zero rows m >= L ----
        if (pos) {
            int c0 = L_ - 64 - i0 + j0;
#pragma unroll
            for (int l = 0; l < 8; l++) {
                int idx = tid + 256 * l;       // 0..2047
                int t = idx & 127;
                int c = (idx >> 7) << 2;
                int m = c0 + t;
                float4 qv = make_float4(0.f, 0.f, 0.f, 0.f);
                if (m < L_) qv = *(const float4*)(Qrptr + (size_t)m * DH + c);
                S.QrT[c + 0][t] = qv.x; S.QrT[c + 1][t] = qv.y;
                S.QrT[c + 2][t] = qv.z; S.QrT[c + 3][t] = qv.w;
            }
        }
        __syncthreads();

        // ---- scores ----
        float s[4][4];
#pragma unroll
        for (int a = 0; a < 4; a++)
#pragma unroll
            for (int b2 = 0; b2 < 4; b2++) s[a][b2] = 0.f;

        if (pos) {
#pragma unroll 16
            for (int d = 0; d < 64; d++) {
                float4 a4 = *(const float4*)&S.qcT[d][ty4];
                float4 k4 = *(const float4*)&S.kT[d][tx4];
                float4 qa = *(const float4*)&S.QrT[d][t0 - 3];
                float4 qb = *(const float4*)&S.QrT[d][t0 + 1];
                float del = S.deltas[d];
                float a[4]  = {a4.x, a4.y, a4.z, a4.w};
                float kv[4] = {k4.x, k4.y, k4.z, k4.w};
                float q8[8] = {qa.x, qa.y, qa.z, qa.w, qb.x, qb.y, qb.z, qb.w};
#pragma unroll
                for (int ii = 0; ii < 4; ii++) {
                    float ap = a[ii] + del;
#pragma unroll
                    for (int jj = 0; jj < 4; jj++)
                        s[ii][jj] += a[ii] * kv[jj] + ap * q8[jj - ii + 3];
                }
            }
        } else {
#pragma unroll 16
            for (int d = 0; d < 64; d++) {
                float4 a4 = *(const float4*)&S.qcT[d][ty4];
                float4 k4 = *(const float4*)&S.kT[d][tx4];
                float a[4]  = {a4.x, a4.y, a4.z, a4.w};
                float kv[4] = {k4.x, k4.y, k4.z, k4.w};
#pragma unroll
                for (int ii = 0; ii < 4; ii++)
#pragma unroll
                    for (int jj = 0; jj < 4; jj++)
                        s[ii][jj] += a[ii] * kv[jj];
            }
        }

        // ---- online softmax: row max ----
#pragma unroll
        for (int ii = 0; ii < 4; ii++) {
            float m = fmaxf(fmaxf(s[ii][0], s[ii][1]), fmaxf(s[ii][2], s[ii][3]));
            S.red[ty4 + ii][tx] = m;
        }
        __syncthreads();
        if (tid < 64) {
            float m = S.red[tid][0];
#pragma unroll
            for (int x = 1; x < 16; x++) m = fmaxf(m, S.red[tid][x]);
            float mOld = S.row_m[tid];
            float mNew = fmaxf(mOld, m);
            S.row_m[tid] = mNew;
            S.row_scale[tid] = __expf(mOld - mNew);
        }
        __syncthreads();

        // ---- P = exp(s - m), partial row sums, rescale O ----
        float psum[4];
#pragma unroll
        for (int ii = 0; ii < 4; ii++) {
            float mN = S.row_m[ty4 + ii];
            float4 pv;
            pv.x = __expf(s[ii][0] - mN);
            pv.y = __expf(s[ii][1] - mN);
            pv.z = __expf(s[ii][2] - mN);
            pv.w = __expf(s[ii][3] - mN);
            psum[ii] = pv.x + pv.y + pv.z + pv.w;
            *(float4*)&S.Ps[ty4 + ii][tx4] = pv;
        }
#pragma unroll
        for (int ii = 0; ii < 4; ii++) S.red[ty4 + ii][tx] = psum[ii];
        float rs[4];
#pragma unroll
        for (int ii = 0; ii < 4; ii++) rs[ii] = S.row_scale[ty4 + ii];
#pragma unroll
        for (int ii = 0; ii < 4; ii++)
#pragma unroll
            for (int dd = 0; dd < 4; dd++) o[ii][dd] *= rs[ii];
        __syncthreads();
        if (tid < 64) {
            float lsum = 0.f;
#pragma unroll
            for (int x = 0; x < 16; x++) lsum += S.red[tid][x];
            S.row_l[tid] = S.row_l[tid] * S.row_scale[tid] + lsum;
        }

        // ---- O += P @ V ----
#pragma unroll 8
        for (int j = 0; j < 64; j++) {
            float p0 = S.Ps[ty4 + 0][j];
            float p1 = S.Ps[ty4 + 1][j];
            float p2 = S.Ps[ty4 + 2][j];
            float p3 = S.Ps[ty4 + 3][j];
            float4 vv = *(const float4*)&S.vs[j][tx4];
            o[0][0] += p0 * vv.x; o[0][1] += p0 * vv.y; o[0][2] += p0 * vv.z; o[0][3] += p0 * vv.w;
            o[1][0] += p1 * vv.x; o[1][1] += p1 * vv.y; o[1][2] += p1 * vv.z; o[1][3] += p1 * vv.w;
            o[2][0] += p2 * vv.x; o[2][1] += p2 * vv.y; o[2][2] += p2 * vv.z; o[2][3] += p2 * vv.w;
            o[3][0] += p3 * vv.x; o[3][1] += p3 * vv.y; o[3][2] += p3 * vv.z; o[3][3] += p3 * vv.w;
        }
        __syncthreads();
    }

    // ---- normalize + store ----
#pragma unroll
    for (int ii = 0; ii < 4; ii++) {
        float inv = 1.0f / S.row_l[ty4 + ii];
        float4 ov = make_float4(o[ii][0] * inv, o[ii][1] * inv,
                                o[ii][2] * inv, o[ii][3] * inv);
        *(float4*)(g_O + ((size_t)(bh * L_ + i0 + ty4 + ii)) * DH + tx4) = ov;
    }
}

// =================================================================
// Output projection: res = Ev + (O @ Wo_w + Wo_b), O gathered from
// head layout. Same GEMM structure as proj_gemm.
// =================================================================
__global__ __launch_bounds__(256, 2)
void oproj_gemm_kernel(const float* __restrict__ Ev,
                       const float* __restrict__ Wo_w,
                       const float* __restrict__ Wo_b) {
    __shared__ float As[16][132];
    __shared__ float Bs[16][128];

    int tid = threadIdx.x;
    int ty = tid >> 4, tx = tid & 15;
    int row0 = blockIdx.y * 128, col0 = blockIdx.x * 128;

    float acc[8][8];
#pragma unroll
    for (int i = 0; i < 8; i++)
#pragma unroll
        for (int j = 0; j < 8; j++) acc[i][j] = 0.f;

    for (int k0 = 0; k0 < D_; k0 += 16) {
#pragma unroll
        for (int l = 0; l < 2; l++) {
            int idx = tid + 256 * l;
            int i = idx >> 2, c = (idx & 3) << 2;
            int r = row0 + i;
            int bb = r >> 10, irow = r & 1023;
            int k = k0 + c;
            int hh = k >> 6, d = k & 63;
            float4 av = *(const float4*)(g_O + ((size_t)((bb * H_ + hh) * L_ + irow)) * DH + d);
            As[c + 0][i] = av.x; As[c + 1][i] = av.y;
            As[c + 2][i] = av.z; As[c + 3][i] = av.w;
            int kk = idx >> 5, cc = (idx & 31) << 2;
            *(float4*)&Bs[kk][cc] = *(const float4*)(Wo_w + (size_t)(k0 + kk) * D_ + col0 + cc);
        }
        __syncthreads();
#pragma unroll
        for (int kk = 0; kk < 16; kk++) {
            float a[8], bv[8];
            *(float4*)(a)     = *(const float4*)&As[kk][ty * 8];
            *(float4*)(a + 4) = *(const float4*)&As[kk][ty * 8 + 4];
            *(float4*)(bv)     = *(const float4*)&Bs[kk][tx * 8];
            *(float4*)(bv + 4) = *(const float4*)&Bs[kk][tx * 8 + 4];
#pragma unroll
            for (int ii = 0; ii < 8; ii++)
#pragma unroll
                for (int jj = 0; jj < 8; jj++)
                    acc[ii][jj] += a[ii] * bv[jj];
        }
        __syncthreads();
    }

#pragma unroll
    for (int ii = 0; ii < 8; ii++) {
        int r = row0 + ty * 8 + ii;
#pragma unroll
        for (int jj = 0; jj < 8; jj += 4) {
            int c = col0 + tx * 8 + jj;
            float4 bv = *(const float4*)(Wo_b + c);
            float4 ev = *(const float4*)(Ev + (size_t)r * D_ + c);
            float4 ov = make_float4(acc[ii][jj] + bv.x + ev.x,
                                    acc[ii][jj + 1] + bv.y + ev.y,
                                    acc[ii][jj + 2] + bv.z + ev.z,
                                    acc[ii][jj + 3] + bv.w + ev.w);
            *(float4*)(g_res + (size_t)r * D_ + c) = ov;
        }
    }
}

// =================================================================
// LayerNorm over rows of 1024. One block per row, 256 threads.
// =================================================================
__global__ __launch_bounds__(256)
void ln_kernel(const float* __restrict__ gamma,
               const float* __restrict__ beta,
               float* __restrict__ out) {
    int row = blockIdx.x;
    int tid = threadIdx.x;
    const float* x = g_res + (size_t)row * D_;
    float4 v = *(const float4*)(x + tid * 4);
    float s  = v.x + v.y + v.z + v.w;
    float ss = v.x * v.x + v.y * v.y + v.z * v.z + v.w * v.w;
#pragma unroll
    for (int off = 16; off > 0; off >>= 1) {
        s  += __shfl_down_sync(0xffffffffu, s,  off);
        ss += __shfl_down_sync(0xffffffffu, ss, off);
    }
    __shared__ float sbuf[8], ssbuf[8];
    __shared__ float mu_s, inv_s;
    int w = tid >> 5;
    if ((tid & 31) == 0) { sbuf[w] = s; ssbuf[w] = ss; }
    __syncthreads();
    if (tid == 0) {
        float st = 0.f, sst = 0.f;
#pragma unroll
        for (int i = 0; i < 8; i++) { st += sbuf[i]; sst += ssbuf[i]; }
        float mu = st * (1.0f / D_);
        float var = sst * (1.0f / D_) - mu * mu;
        mu_s = mu;
        inv_s = rsqrtf(var + 1e-5f);
    }
    __syncthreads();
    float mu = mu_s, inv = inv_s;
    float4 g4 = *(const float4*)(gamma + tid * 4);
    float4 b4 = *(const float4*)(beta + tid * 4);
    float4 o4;
    o4.x = (v.x - mu) * inv * g4.x + b4.x;
    o4.y = (v.y - mu) * inv * g4.y + b4.y;
    o4.z = (v.z - mu) * inv * g4.z + b4.z;
    o4.w = (v.w - mu) * inv * g4.w + b4.w;
    *(float4*)(out + (size_t)row * D_ + tid * 4) = o4;
}

// =================================================================
extern "C" void kernel_launch(void* const* d_in, const int* in_sizes, int n_in,
                              void* d_out, int out_size) {
    const float* E    = (const float*)d_in[0];
    const float* Ev   = (const float*)d_in[1];
    const float* R    = (const float*)d_in[2];
    const float* Wq   = (const float*)d_in[3];
    const float* Wke  = (const float*)d_in[4];
    const float* Wkr  = (const float*)d_in[5];
    const float* Wv   = (const float*)d_in[6];
    const float* cb   = (const float*)d_in[7];
    const float* pb   = (const float*)d_in[8];
    const float* Wo_w = (const float*)d_in[9];
    const float* Wo_b = (const float*)d_in[10];
    const float* ln_g = (const float*)d_in[11];
    const float* ln_b = (const float*)d_in[12];
    float* out = (float*)d_out;

    cudaFuncSetAttribute(attn_kernel, cudaFuncAttributeMaxDynamicSharedMemorySize,
                         (int)sizeof(AttnSmem));

    dim3 pg(D_ / 128, (B_ * L_) / 128, 4);          // (8,16,4)
    proj_gemm_kernel<<<pg, 256>>>(E, Ev, R, Wq, Wke, Wkr, Wv);

    dim3 ag(L_ / 64, B_ * H_);                      // (16,32)
    attn_kernel<<<ag, 256, sizeof(AttnSmem)>>>(cb, pb);

    dim3 og(D_ / 128, (B_ * L_) / 128);             // (8,16)
    oproj_gemm_kernel<<<og, 256>>>(Ev, Wo_w, Wo_b);

    ln_kernel<<<B_ * L_, 256>>>(ln_g, ln_b, out);
}

// round 4
// speedup vs baseline: 1.3074x; 1.3074x over previous
#include <cuda_runtime.h>
#include <cuda_bf16.h>

#define B_ 2
#define L_ 1024
#define D_ 1024
#define H_ 16
#define DH 64

// ---------------- scratch (no cudaMalloc allowed) ----------------
__device__ float g_q[B_*H_*L_*DH];      // head layout [b][h][i][d]
__device__ float g_k[B_*H_*L_*DH];
__device__ float g_v[B_*H_*L_*DH];
__device__ float g_Qr[H_*L_*DH];        // [h][m][d]
__device__ float g_O[B_*H_*L_*DH];      // attention output, head layout
__device__ float g_res[B_*L_*D_];       // residual before LN

// bf16 hi/lo split operands for mma GEMMs
__device__ __nv_bfloat16 g_Ehi [B_*L_*D_], g_Elo [B_*L_*D_];
__device__ __nv_bfloat16 g_Evhi[B_*L_*D_], g_Evlo[B_*L_*D_];
__device__ __nv_bfloat16 g_Rhi [L_*D_],    g_Rlo [L_*D_];
__device__ __nv_bfloat16 g_WThi[5*D_*D_],  g_WTlo[5*D_*D_];   // transposed [N][K]: 0 Wq,1 Wke,2 Wv,3 Wkr,4 Wo
__device__ __nv_bfloat16 g_Ohi [B_*L_*D_], g_Olo [B_*L_*D_];

__device__ __forceinline__ void split_bf16(float x, __nv_bfloat16& hi, __nv_bfloat16& lo) {
    hi = __float2bfloat16(x);
    lo = __float2bfloat16(x - __bfloat162float(hi));
}

__device__ __forceinline__ void mma_bf16(float* c,
                                         unsigned a0, unsigned a1, unsigned a2, unsigned a3,
                                         unsigned b0, unsigned b1) {
    asm volatile(
        "mma.sync.aligned.m16n8k16.row.col.f32.bf16.bf16.f32 "
        "{%0,%1,%2,%3}, {%4,%5,%6,%7}, {%8,%9}, {%0,%1,%2,%3};"
        : "+f"(c[0]), "+f"(c[1]), "+f"(c[2]), "+f"(c[3])
        : "r"(a0), "r"(a1), "r"(a2), "r"(a3), "r"(b0), "r"(b1));
}

// =================================================================
// Pre-pass 1: split-convert activations E, Ev, R -> hi/lo bf16
// =================================================================
__global__ __launch_bounds__(256)
void split_convert_kernel(const float* __restrict__ E,
                          const float* __restrict__ Ev,
                          const float* __restrict__ R) {
    int z = blockIdx.z;
    const float* src = (z == 0) ? E : (z == 1) ? Ev : R;
    __nv_bfloat16* hi = (z == 0) ? g_Ehi : (z == 1) ? g_Evhi : g_Rhi;
    __nv_bfloat16* lo = (z == 0) ? g_Elo : (z == 1) ? g_Evlo : g_Rlo;
    int n4 = (z == 2) ? (L_ * D_ / 4) : (B_ * L_ * D_ / 4);
    int i = blockIdx.x * 256 + threadIdx.x;
    if (i >= n4) return;
    float4 v = ((const float4*)src)[i];
    __nv_bfloat16 hx, lx, hy, ly, hz, lz, hw, lw;
    split_bf16(v.x, hx, lx); split_bf16(v.y, hy, ly);
    split_bf16(v.z, hz, lz); split_bf16(v.w, hw, lw);
    __nv_bfloat162 h0; h0.x = hx; h0.y = hy;
    __nv_bfloat162 h1; h1.x = hz; h1.y = hw;
    __nv_bfloat162 l0; l0.x = lx; l0.y = ly;
    __nv_bfloat162 l1; l1.x = lz; l1.y = lw;
    ((__nv_bfloat162*)hi)[2 * i]     = h0;
    ((__nv_bfloat162*)hi)[2 * i + 1] = h1;
    ((__nv_bfloat162*)lo)[2 * i]     = l0;
    ((__nv_bfloat162*)lo)[2 * i + 1] = l1;
}

// =================================================================
// Pre-pass 2: transpose + split-convert weights [K][N] -> [N][K] hi/lo
// =================================================================
__global__ __launch_bounds__(256)
void wt_convert_kernel(const float* __restrict__ Wq, const float* __restrict__ Wke,
                       const float* __restrict__ Wv, const float* __restrict__ Wkr,
                       const float* __restrict__ Wo) {
    int z = blockIdx.z;
    const float* W = (z == 0) ? Wq : (z == 1) ? Wke : (z == 2) ? Wv : (z == 3) ? Wkr : Wo;
    __nv_bfloat16* hi = g_WThi + (size_t)z * D_ * D_;
    __nv_bfloat16* lo = g_WTlo + (size_t)z * D_ * D_;
    __shared__ float tbuf[32][33];
    int tx = threadIdx.x & 31, ty = threadIdx.x >> 5;   // 32 x 8
    int nn0 = blockIdx.x * 32, kk0 = blockIdx.y * 32;
#pragma unroll
    for (int i = 0; i < 4; i++)
        tbuf[ty * 4 + i][tx] = W[(size_t)(kk0 + ty * 4 + i) * D_ + nn0 + tx];
    __syncthreads();
#pragma unroll
    for (int i = 0; i < 4; i++) {
        float v = tbuf[tx][ty * 4 + i];
        __nv_bfloat16 h, l;
        split_bf16(v, h, l);
        size_t off = (size_t)(nn0 + ty * 4 + i) * D_ + kk0 + tx;
        hi[off] = h;
        lo[off] = l;
    }
}

// =================================================================
// Pre-pass 3 (after attention): gather g_O head-layout -> row-major hi/lo
// =================================================================
__global__ __launch_bounds__(256)
void o_convert_kernel() {
    int i = blockIdx.x * 256 + threadIdx.x;          // per float4
    float4 v = ((const float4*)g_O)[i];
    int idx = i * 4;
    int d = idx & 63;
    int rest = idx >> 6;
    int ir = rest & 1023;
    int bh = rest >> 10;
    int bb = bh >> 4, hh = bh & 15;
    size_t off = ((size_t)(bb * 1024 + ir) * D_ + hh * 64 + d);
    __nv_bfloat16 hx, lx, hy, ly, hz, lz, hw, lw;
    split_bf16(v.x, hx, lx); split_bf16(v.y, hy, ly);
    split_bf16(v.z, hz, lz); split_bf16(v.w, hw, lw);
    __nv_bfloat162 h0; h0.x = hx; h0.y = hy;
    __nv_bfloat162 h1; h1.x = hz; h1.y = hw;
    __nv_bfloat162 l0; l0.x = lx; l0.y = ly;
    __nv_bfloat162 l1; l1.x = lz; l1.y = lw;
    *(__nv_bfloat162*)(g_Ohi + off)     = h0;
    *(__nv_bfloat162*)(g_Ohi + off + 2) = h1;
    *(__nv_bfloat162*)(g_Olo + off)     = l0;
    *(__nv_bfloat162*)(g_Olo + off + 2) = l1;
}

// =================================================================
// Split-bf16 GEMM via mma.sync.m16n8k16 (legacy HMMA path, base sm_103).
// C = A(hi+lo) @ B(hi+lo)^T with 3-term correction, fp32 accumulate.
// 128x128 CTA tile, 8 warps (2 m x 4 n of 64x32), K-chunk 32, double buffer.
// phase 0: q/k/v/Qr projections (grid 448).  phase 1: oproj (grid 128).
// =================================================================
#define KC 32
#define SROW 80                     // bytes per smem row (40 bf16, conflict-free)
#define MAT_BYTES (128 * SROW)      // 10240
#define STAGE_BYTES (4 * MAT_BYTES) // 40960
#define GEMM_SMEM (2 * STAGE_BYTES) // 81920

__global__ __launch_bounds__(256)
void mma_gemm_kernel(int phase, const float* __restrict__ Ev,
                     const float* __restrict__ Wo_b) {
    extern __shared__ __align__(16) char sm[];
    int tid = threadIdx.x;
    int lane = tid & 31, wid = tid >> 5;

    // ---- tile decode ----
    int t = blockIdx.x;
    const __nv_bfloat16 *Ahi, *Alo;
    int row0, col0, which;
    if (phase == 0) {
        if (t < 384) {
            which = t >> 7;
            int loc = t & 127;
            row0 = (loc >> 3) * 128;
            col0 = (loc & 7) * 128;
            if (which == 0) { Ahi = g_Ehi;  Alo = g_Elo;  }
            else            { Ahi = g_Evhi; Alo = g_Evlo; }
        } else {
            which = 3;
            int loc = t - 384;
            row0 = (loc >> 3) * 128;
            col0 = (loc & 7) * 128;
            Ahi = g_Rhi; Alo = g_Rlo;
        }
    } else {
        which = 4;
        row0 = (t >> 3) * 128;
        col0 = (t & 7) * 128;
        Ahi = g_Ohi; Alo = g_Olo;
    }
    const __nv_bfloat16* Bhi = g_WThi + (size_t)which * D_ * D_;
    const __nv_bfloat16* Blo = g_WTlo + (size_t)which * D_ * D_;

    const int wm = (wid >> 2) * 64;     // warp m offset
    const int wn = (wid & 3) * 32;      // warp n offset

    float c[4][4][4];
#pragma unroll
    for (int a = 0; a < 4; a++)
#pragma unroll
        for (int b = 0; b < 4; b++)
#pragma unroll
            for (int e = 0; e < 4; e++) c[a][b][e] = 0.f;

    uint4 pr[8];

    // prefetch chunk 0
    {
#pragma unroll
        for (int l = 0; l < 2; l++) {
            int idx = tid + 256 * l;
            int row = idx >> 2, colc = (idx & 3) * 8;
            size_t ga = (size_t)(row0 + row) * D_ + colc;
            size_t gb = (size_t)(col0 + row) * D_ + colc;
            pr[l * 4 + 0] = *(const uint4*)(Ahi + ga);
            pr[l * 4 + 1] = *(const uint4*)(Alo + ga);
            pr[l * 4 + 2] = *(const uint4*)(Bhi + gb);
            pr[l * 4 + 3] = *(const uint4*)(Blo + gb);
        }
        char* base = sm;
#pragma unroll
        for (int l = 0; l < 2; l++) {
            int idx = tid + 256 * l;
            int row = idx >> 2, colc = (idx & 3) * 8;
            int so = row * SROW + colc * 2;
            *(uint4*)(base + so)                 = pr[l * 4 + 0];
            *(uint4*)(base + MAT_BYTES + so)     = pr[l * 4 + 1];
            *(uint4*)(base + 2 * MAT_BYTES + so) = pr[l * 4 + 2];
            *(uint4*)(base + 3 * MAT_BYTES + so) = pr[l * 4 + 3];
        }
    }
    __syncthreads();

    for (int ch = 0; ch < D_ / KC; ch++) {
        // prefetch next chunk into registers
        if (ch + 1 < D_ / KC) {
            int kc0 = (ch + 1) * KC;
#pragma unroll
            for (int l = 0; l < 2; l++) {
                int idx = tid + 256 * l;
                int row = idx >> 2, colc = (idx & 3) * 8;
                size_t ga = (size_t)(row0 + row) * D_ + kc0 + colc;
                size_t gb = (size_t)(col0 + row) * D_ + kc0 + colc;
                pr[l * 4 + 0] = *(const uint4*)(Ahi + ga);
                pr[l * 4 + 1] = *(const uint4*)(Alo + ga);
                pr[l * 4 + 2] = *(const uint4*)(Bhi + gb);
                pr[l * 4 + 3] = *(const uint4*)(Blo + gb);
            }
        }

        // compute current chunk
        {
            const char* base = sm + (ch & 1) * STAGE_BYTES;
#pragma unroll
            for (int ks = 0; ks < 2; ks++) {
                int kb = ks * 32;     // 16 bf16 = 32 bytes
                unsigned bh[4][2], bl[4][2];
#pragma unroll
                for (int nt = 0; nt < 4; nt++) {
                    const char* bp = base + 2 * MAT_BYTES +
                        (wn + nt * 8 + (lane >> 2)) * SROW + kb + (lane & 3) * 4;
                    bh[nt][0] = *(const unsigned*)bp;
                    bh[nt][1] = *(const unsigned*)(bp + 16);
                    bl[nt][0] = *(const unsigned*)(bp + MAT_BYTES);
                    bl[nt][1] = *(const unsigned*)(bp + MAT_BYTES + 16);
                }
#pragma unroll
                for (int mt = 0; mt < 4; mt++) {
                    const char* ap = base +
                        (wm + mt * 16 + (lane >> 2)) * SROW + kb + (lane & 3) * 4;
                    unsigned a0 = *(const unsigned*)ap;
                    unsigned a1 = *(const unsigned*)(ap + 8 * SROW);
                    unsigned a2 = *(const unsigned*)(ap + 16);
                    unsigned a3 = *(const unsigned*)(ap + 8 * SROW + 16);
                    unsigned l0 = *(const unsigned*)(ap + MAT_BYTES);
                    unsigned l1 = *(const unsigned*)(ap + MAT_BYTES + 8 * SROW);
                    unsigned l2 = *(const unsigned*)(ap + MAT_BYTES + 16);
                    unsigned l3 = *(const unsigned*)(ap + MAT_BYTES + 8 * SROW + 16);
#pragma unroll
                    for (int nt = 0; nt < 4; nt++) {
                        mma_bf16(c[mt][nt], a0, a1, a2, a3, bh[nt][0], bh[nt][1]);
                        mma_bf16(c[mt][nt], l0, l1, l2, l3, bh[nt][0], bh[nt][1]);
                        mma_bf16(c[mt][nt], a0, a1, a2, a3, bl[nt][0], bl[nt][1]);
                    }
                }
            }
        }

        // store prefetched regs to the other stage
        if (ch + 1 < D_ / KC) {
            char* base = sm + ((ch + 1) & 1) * STAGE_BYTES;
#pragma unroll
            for (int l = 0; l < 2; l++) {
                int idx = tid + 256 * l;
                int row = idx >> 2, colc = (idx & 3) * 8;
                int so = row * SROW + colc * 2;
                *(uint4*)(base + so)                 = pr[l * 4 + 0];
                *(uint4*)(base + MAT_BYTES + so)     = pr[l * 4 + 1];
                *(uint4*)(base + 2 * MAT_BYTES + so) = pr[l * 4 + 2];
                *(uint4*)(base + 3 * MAT_BYTES + so) = pr[l * 4 + 3];
            }
        }
        __syncthreads();
    }

    // ---- epilogue ----
#pragma unroll
    for (int mt = 0; mt < 4; mt++) {
#pragma unroll
        for (int nt = 0; nt < 4; nt++) {
            int r   = row0 + wm + mt * 16 + (lane >> 2);
            int col = col0 + wn + nt * 8 + (lane & 3) * 2;
            float2 lo2 = make_float2(c[mt][nt][0], c[mt][nt][1]);
            float2 hi2 = make_float2(c[mt][nt][2], c[mt][nt][3]);
            if (phase == 0) {
                int hh = col >> 6, d = col & 63;
                float* dst0;
                float* dst1;
                if (which == 3) {
                    dst0 = g_Qr + ((size_t)(hh * L_ + r)) * DH + d;
                    dst1 = g_Qr + ((size_t)(hh * L_ + r + 8)) * DH + d;
                } else {
                    float* outb = (which == 0) ? g_q : (which == 1) ? g_k : g_v;
                    int bb = r >> 10, ir = r & 1023;
                    dst0 = outb + ((size_t)((bb * H_ + hh) * L_ + ir)) * DH + d;
                    dst1 = outb + ((size_t)((bb * H_ + hh) * L_ + ir + 8)) * DH + d;
                }
                *(float2*)dst0 = lo2;
                *(float2*)dst1 = hi2;
            } else {
                float2 wb = *(const float2*)(Wo_b + col);
                float2 e0 = *(const float2*)(Ev + (size_t)r * D_ + col);
                float2 e1 = *(const float2*)(Ev + (size_t)(r + 8) * D_ + col);
                float2 o0 = make_float2(lo2.x + wb.x + e0.x, lo2.y + wb.y + e0.y);
                float2 o1 = make_float2(hi2.x + wb.x + e1.x, hi2.y + wb.y + e1.y);
                *(float2*)(g_res + (size_t)r * D_ + col) = o0;
                *(float2*)(g_res + (size_t)(r + 8) * D_ + col) = o1;
            }
        }
    }
}

// =================================================================
// Fused relative attention with online softmax (unchanged, passing).
// =================================================================
struct AttnSmem {
    float qcT[64][68];
    float kT [64][68];
    float vs [64][68];
    float QrT[64][132];
    float Ps [64][68];
    float deltas[64];
    float red[64][17];
    float row_m[64], row_l[64], row_scale[64];
};

__global__ __launch_bounds__(256, 2)
void attn_kernel(const float* __restrict__ cb, const float* __restrict__ pb) {
    extern __shared__ float smem_raw[];
    AttnSmem& S = *reinterpret_cast<AttnSmem*>(smem_raw);

    int tid = threadIdx.x;
    int ty = tid >> 4, tx = tid & 15;
    int ty4 = ty * 4, tx4 = tx * 4;
    int ib = blockIdx.x;
    int bh = blockIdx.y;
    int h = bh & 15;
    int i0 = ib * 64;

    const float* qptr  = g_q  + (size_t)bh * L_ * DH;
    const float* kptr  = g_k  + (size_t)bh * L_ * DH;
    const float* vptr  = g_v  + (size_t)bh * L_ * DH;
    const float* Qrptr = g_Qr + (size_t)h  * L_ * DH;

    if (tid < 64) {
        S.row_m[tid] = -1e30f;
        S.row_l[tid] = 0.f;
        S.deltas[tid] = pb[h * DH + tid] - cb[h * DH + tid];
    }
#pragma unroll
    for (int l = 0; l < 4; l++) {
        int idx = tid + 256 * l;
        int i = idx & 63;
        int c = (idx >> 6) << 2;
        float4 qv = *(const float4*)(qptr + (size_t)(i0 + i) * DH + c);
        S.qcT[c + 0][i] = qv.x + cb[h * DH + c + 0];
        S.qcT[c + 1][i] = qv.y + cb[h * DH + c + 1];
        S.qcT[c + 2][i] = qv.z + cb[h * DH + c + 2];
        S.qcT[c + 3][i] = qv.w + cb[h * DH + c + 3];
    }

    float o[4][4];
#pragma unroll
    for (int a = 0; a < 4; a++)
#pragma unroll
        for (int b2 = 0; b2 < 4; b2++) o[a][b2] = 0.f;

    const int t0 = tx4 - ty4 + 63;

    for (int jt = 0; jt < 16; jt++) {
        int j0 = jt * 64;
        bool pos = (j0 <= i0);

#pragma unroll
        for (int l = 0; l < 4; l++) {
            int idx = tid + 256 * l;
            int i = idx & 63;
            int c = (idx >> 6) << 2;
            float4 kv = *(const float4*)(kptr + (size_t)(j0 + i) * DH + c);
            S.kT[c + 0][i] = kv.x; S.kT[c + 1][i] = kv.y;
            S.kT[c + 2][i] = kv.z; S.kT[c + 3][i] = kv.w;
            float4 vv = *(const float4*)(vptr + (size_t)(j0 + i) * DH + c);
            *(float4*)&S.vs[i][c] = vv;
        }
        if (pos) {
            int c0 = L_ - 64 - i0 + j0;
#pragma unroll
            for (int l = 0; l < 8; l++) {
                int idx = tid + 256 * l;
                int t = idx & 127;
                int c = (idx >> 7) << 2;
                int m = c0 + t;
                float4 qv = make_float4(0.f, 0.f, 0.f, 0.f);
                if (m < L_) qv = *(const float4*)(Qrptr + (size_t)m * DH + c);
                S.QrT[c + 0][t] = qv.x; S.QrT[c + 1][t] = qv.y;
                S.QrT[c + 2][t] = qv.z; S.QrT[c + 3][t] = qv.w;
            }
        }
        __syncthreads();

        float s[4][4];
#pragma unroll
        for (int a = 0; a < 4; a++)
#pragma unroll
            for (int b2 = 0; b2 < 4; b2++) s[a][b2] = 0.f;

        if (pos) {
#pragma unroll 16
            for (int d = 0; d < 64; d++) {
                float4 a4 = *(const float4*)&S.qcT[d][ty4];
                float4 k4 = *(const float4*)&S.kT[d][tx4];
                float4 qa = *(const float4*)&S.QrT[d][t0 - 3];
                float4 qb = *(const float4*)&S.QrT[d][t0 + 1];
                float del = S.deltas[d];
                float a[4]  = {a4.x, a4.y, a4.z, a4.w};
                float kv[4] = {k4.x, k4.y, k4.z, k4.w};
                float q8[8] = {qa.x, qa.y, qa.z, qa.w, qb.x, qb.y, qb.z, qb.w};
#pragma unroll
                for (int ii = 0; ii < 4; ii++) {
                    float ap = a[ii] + del;
#pragma unroll
                    for (int jj = 0; jj < 4; jj++)
                        s[ii][jj] += a[ii] * kv[jj] + ap * q8[jj - ii + 3];
                }
            }
        } else {
#pragma unroll 16
            for (int d = 0; d < 64; d++) {
                float4 a4 = *(const float4*)&S.qcT[d][ty4];
                float4 k4 = *(const float4*)&S.kT[d][tx4];
                float a[4]  = {a4.x, a4.y, a4.z, a4.w};
                float kv[4] = {k4.x, k4.y, k4.z, k4.w};
#pragma unroll
                for (int ii = 0; ii < 4; ii++)
#pragma unroll
                    for (int jj = 0; jj < 4; jj++)
                        s[ii][jj] += a[ii] * kv[jj];
            }
        }

#pragma unroll
        for (int ii = 0; ii < 4; ii++) {
            float m = fmaxf(fmaxf(s[ii][0], s[ii][1]), fmaxf(s[ii][2], s[ii][3]));
            S.red[ty4 + ii][tx] = m;
        }
        __syncthreads();
        if (tid < 64) {
            float m = S.red[tid][0];
#pragma unroll
            for (int x = 1; x < 16; x++) m = fmaxf(m, S.red[tid][x]);
            float mOld = S.row_m[tid];
            float mNew = fmaxf(mOld, m);
            S.row_m[tid] = mNew;
            S.row_scale[tid] = __expf(mOld - mNew);
        }
        __syncthreads();

        float psum[4];
#pragma unroll
        for (int ii = 0; ii < 4; ii++) {
            float mN = S.row_m[ty4 + ii];
            float4 pv;
            pv.x = __expf(s[ii][0] - mN);
            pv.y = __expf(s[ii][1] - mN);
            pv.z = __expf(s[ii][2] - mN);
            pv.w = __expf(s[ii][3] - mN);
            psum[ii] = pv.x + pv.y + pv.z + pv.w;
            *(float4*)&S.Ps[ty4 + ii][tx4] = pv;
        }
#pragma unroll
        for (int ii = 0; ii < 4; ii++) S.red[ty4 + ii][tx] = psum[ii];
        float rs[4];
#pragma unroll
        for (int ii = 0; ii < 4; ii++) rs[ii] = S.row_scale[ty4 + ii];
#pragma unroll
        for (int ii = 0; ii < 4; ii++)
#pragma unroll
            for (int dd = 0; dd < 4; dd++) o[ii][dd] *= rs[ii];
        __syncthreads();
        if (tid < 64) {
            float lsum = 0.f;
#pragma unroll
            for (int x = 0; x < 16; x++) lsum += S.red[tid][x];
            S.row_l[tid] = S.row_l[tid] * S.row_scale[tid] + lsum;
        }

#pragma unroll 8
        for (int j = 0; j < 64; j++) {
            float p0 = S.Ps[ty4 + 0][j];
            float p1 = S.Ps[ty4 + 1][j];
            float p2 = S.Ps[ty4 + 2][j];
            float p3 = S.Ps[ty4 + 3][j];
            float4 vv = *(const float4*)&S.vs[j][tx4];
            o[0][0] += p0 * vv.x; o[0][1] += p0 * vv.y; o[0][2] += p0 * vv.z; o[0][3] += p0 * vv.w;
            o[1][0] += p1 * vv.x; o[1][1] += p1 * vv.y; o[1][2] += p1 * vv.z; o[1][3] += p1 * vv.w;
            o[2][0] += p2 * vv.x; o[2][1] += p2 * vv.y; o[2][2] += p2 * vv.z; o[2][3] += p2 * vv.w;
            o[3][0] += p3 * vv.x; o[3][1] += p3 * vv.y; o[3][2] += p3 * vv.z; o[3][3] += p3 * vv.w;
        }
        __syncthreads();
    }

#pragma unroll
    for (int ii = 0; ii < 4; ii++) {
        float inv = 1.0f / S.row_l[ty4 + ii];
        float4 ov = make_float4(o[ii][0] * inv, o[ii][1] * inv,
                                o[ii][2] * inv, o[ii][3] * inv);
        *(float4*)(g_O + ((size_t)(bh * L_ + i0 + ty4 + ii)) * DH + tx4) = ov;
    }
}

// =================================================================
// LayerNorm (unchanged).
// =================================================================
__global__ __launch_bounds__(256)
void ln_kernel(const float* __restrict__ gamma,
               const float* __restrict__ beta,
               float* __restrict__ out) {
    int row = blockIdx.x;
    int tid = threadIdx.x;
    const float* x = g_res + (size_t)row * D_;
    float4 v = *(const float4*)(x + tid * 4);
    float s  = v.x + v.y + v.z + v.w;
    float ss = v.x * v.x + v.y * v.y + v.z * v.z + v.w * v.w;
#pragma unroll
    for (int off = 16; off > 0; off >>= 1) {
        s  += __shfl_down_sync(0xffffffffu, s,  off);
        ss += __shfl_down_sync(0xffffffffu, ss, off);
    }
    __shared__ float sbuf[8], ssbuf[8];
    __shared__ float mu_s, inv_s;
    int w = tid >> 5;
    if ((tid & 31) == 0) { sbuf[w] = s; ssbuf[w] = ss; }
    __syncthreads();
    if (tid == 0) {
        float st = 0.f, sst = 0.f;
#pragma unroll
        for (int i = 0; i < 8; i++) { st += sbuf[i]; sst += ssbuf[i]; }
        float mu = st * (1.0f / D_);
        float var = sst * (1.0f / D_) - mu * mu;
        mu_s = mu;
        inv_s = rsqrtf(var + 1e-5f);
    }
    __syncthreads();
    float mu = mu_s, inv = inv_s;
    float4 g4 = *(const float4*)(gamma + tid * 4);
    float4 b4 = *(const float4*)(beta + tid * 4);
    float4 o4;
    o4.x = (v.x - mu) * inv * g4.x + b4.x;
    o4.y = (v.y - mu) * inv * g4.y + b4.y;
    o4.z = (v.z - mu) * inv * g4.z + b4.z;
    o4.w = (v.w - mu) * inv * g4.w + b4.w;
    *(float4*)(out + (size_t)row * D_ + tid * 4) = o4;
}

// =================================================================
extern "C" void kernel_launch(void* const* d_in, const int* in_sizes, int n_in,
                              void* d_out, int out_size) {
    const float* E    = (const float*)d_in[0];
    const float* Ev   = (const float*)d_in[1];
    const float* R    = (const float*)d_in[2];
    const float* Wq   = (const float*)d_in[3];
    const float* Wke  = (const float*)d_in[4];
    const float* Wkr  = (const float*)d_in[5];
    const float* Wv   = (const float*)d_in[6];
    const float* cb   = (const float*)d_in[7];
    const float* pb   = (const float*)d_in[8];
    const float* Wo_w = (const float*)d_in[9];
    const float* Wo_b = (const float*)d_in[10];
    const float* ln_g = (const float*)d_in[11];
    const float* ln_b = (const float*)d_in[12];
    float* out = (float*)d_out;

    cudaFuncSetAttribute(attn_kernel, cudaFuncAttributeMaxDynamicSharedMemorySize,
                         (int)sizeof(AttnSmem));
    cudaFuncSetAttribute(mma_gemm_kernel, cudaFuncAttributeMaxDynamicSharedMemorySize,
                         GEMM_SMEM);

    // hi/lo split converts
    dim3 sg(B_ * L_ * D_ / 4 / 256, 1, 3);
    split_convert_kernel<<<sg, 256>>>(E, Ev, R);
    dim3 wg(D_ / 32, D_ / 32, 5);
    wt_convert_kernel<<<wg, 256>>>(Wq, Wke, Wv, Wkr, Wo_w);

    // q/k/v/Qr projections on tensor cores (legacy mma path)
    mma_gemm_kernel<<<448, 256, GEMM_SMEM>>>(0, Ev, Wo_b);

    // fused attention
    dim3 ag(L_ / 64, B_ * H_);
    attn_kernel<<<ag, 256, sizeof(AttnSmem)>>>(cb, pb);

    // gather + split O, output projection on tensor cores
    o_convert_kernel<<<B_ * L_ * D_ / 4 / 256, 256>>>();
    mma_gemm_kernel<<<128, 256, GEMM_SMEM>>>(1, Ev, Wo_b);

    ln_kernel<<<B_ * L_, 256>>>(ln_g, ln_b, out);
}

// round 7
// speedup vs baseline: 2.1955x; 1.6793x over previous
#include <cuda_runtime.h>
#include <cuda_bf16.h>
#include <cuda_fp16.h>

#define B_ 2
#define L_ 1024
#define D_ 1024
#define H_ 16
#define DH 64

// ---------------- scratch (no cudaMalloc allowed) ----------------
__device__ float g_O[B_*H_*L_*DH];      // attention output, head layout
__device__ float g_res[B_*L_*D_];       // residual before LN

// bf16 hi/lo split operands for projection GEMMs
__device__ __nv_bfloat16 g_Ehi [B_*L_*D_], g_Elo [B_*L_*D_];
__device__ __nv_bfloat16 g_Evhi[B_*L_*D_], g_Evlo[B_*L_*D_];
__device__ __nv_bfloat16 g_Rhi [L_*D_],    g_Rlo [L_*D_];
__device__ __nv_bfloat16 g_WThi[5*D_*D_],  g_WTlo[5*D_*D_];   // transposed [N][K]
__device__ __nv_bfloat16 g_Ohi [B_*L_*D_], g_Olo [B_*L_*D_];

// fp16 hi/lo operands for mma attention (head layout [b][h][i][d])
__device__ __half g_qch[B_*H_*L_*DH], g_qcl[B_*H_*L_*DH];   // q + cb
__device__ __half g_kh [B_*H_*L_*DH], g_kl [B_*H_*L_*DH];
__device__ __half g_vh [B_*H_*L_*DH], g_vl [B_*H_*L_*DH];
__device__ __half g_Qrh[H_*L_*DH],    g_Qrl[H_*L_*DH];      // [h][m][d]

__device__ __forceinline__ void split_bf16(float x, __nv_bfloat16& hi, __nv_bfloat16& lo) {
    hi = __float2bfloat16(x);
    lo = __float2bfloat16(x - __bfloat162float(hi));
}
__device__ __forceinline__ unsigned smem_u32(const void* p) {
    unsigned a;
    asm("{ .reg .u64 t; cvta.to.shared.u64 t, %1; cvt.u32.u64 %0, t; }" : "=r"(a) : "l"(p));
    return a;
}
__device__ __forceinline__ void mma_bf16(float* c,
                                         unsigned a0, unsigned a1, unsigned a2, unsigned a3,
                                         unsigned b0, unsigned b1) {
    asm volatile(
        "mma.sync.aligned.m16n8k16.row.col.f32.bf16.bf16.f32 "
        "{%0,%1,%2,%3}, {%4,%5,%6,%7}, {%8,%9}, {%0,%1,%2,%3};"
        : "+f"(c[0]), "+f"(c[1]), "+f"(c[2]), "+f"(c[3])
        : "r"(a0), "r"(a1), "r"(a2), "r"(a3), "r"(b0), "r"(b1));
}
__device__ __forceinline__ void mma_f16(float* c,
                                        unsigned a0, unsigned a1, unsigned a2, unsigned a3,
                                        unsigned b0, unsigned b1) {
    asm volatile(
        "mma.sync.aligned.m16n8k16.row.col.f32.f16.f16.f32 "
        "{%0,%1,%2,%3}, {%4,%5,%6,%7}, {%8,%9}, {%0,%1,%2,%3};"
        : "+f"(c[0]), "+f"(c[1]), "+f"(c[2]), "+f"(c[3])
        : "r"(a0), "r"(a1), "r"(a2), "r"(a3), "r"(b0), "r"(b1));
}
__device__ __forceinline__ void ldsm_x4(unsigned& r0, unsigned& r1, unsigned& r2, unsigned& r3,
                                        unsigned addr) {
    asm volatile("ldmatrix.sync.aligned.m8n8.x4.shared.b16 {%0,%1,%2,%3}, [%4];"
                 : "=r"(r0), "=r"(r1), "=r"(r2), "=r"(r3) : "r"(addr));
}
__device__ __forceinline__ void ldsm_x4_t(unsigned& r0, unsigned& r1, unsigned& r2, unsigned& r3,
                                          unsigned addr) {
    asm volatile("ldmatrix.sync.aligned.m8n8.x4.trans.shared.b16 {%0,%1,%2,%3}, [%4];"
                 : "=r"(r0), "=r"(r1), "=r"(r2), "=r"(r3) : "r"(addr));
}
__device__ __forceinline__ unsigned pack_h2(__half a, __half b) {
    __half2 h; h.x = a; h.y = b;
    return *reinterpret_cast<unsigned*>(&h);
}

// =================================================================
// Pre-pass 1: split-convert activations E, Ev, R -> hi/lo bf16
// =================================================================
__global__ __launch_bounds__(256)
void split_convert_kernel(const float* __restrict__ E,
                          const float* __restrict__ Ev,
                          const float* __restrict__ R) {
    int z = blockIdx.z;
    const float* src = (z == 0) ? E : (z == 1) ? Ev : R;
    __nv_bfloat16* hi = (z == 0) ? g_Ehi : (z == 1) ? g_Evhi : g_Rhi;
    __nv_bfloat16* lo = (z == 0) ? g_Elo : (z == 1) ? g_Evlo : g_Rlo;
    int n4 = (z == 2) ? (L_ * D_ / 4) : (B_ * L_ * D_ / 4);
    int i = blockIdx.x * 256 + threadIdx.x;
    if (i >= n4) return;
    float4 v = ((const float4*)src)[i];
    __nv_bfloat16 hx, lx, hy, ly, hz, lz, hw, lw;
    split_bf16(v.x, hx, lx); split_bf16(v.y, hy, ly);
    split_bf16(v.z, hz, lz); split_bf16(v.w, hw, lw);
    __nv_bfloat162 h0; h0.x = hx; h0.y = hy;
    __nv_bfloat162 h1; h1.x = hz; h1.y = hw;
    __nv_bfloat162 l0; l0.x = lx; l0.y = ly;
    __nv_bfloat162 l1; l1.x = lz; l1.y = lw;
    ((__nv_bfloat162*)hi)[2 * i]     = h0;
    ((__nv_bfloat162*)hi)[2 * i + 1] = h1;
    ((__nv_bfloat162*)lo)[2 * i]     = l0;
    ((__nv_bfloat162*)lo)[2 * i + 1] = l1;
}

// =================================================================
// Pre-pass 2: transpose + split-convert weights [K][N] -> [N][K] hi/lo
// =================================================================
__global__ __launch_bounds__(256)
void wt_convert_kernel(const float* __restrict__ Wq, const float* __restrict__ Wke,
                       const float* __restrict__ Wv, const float* __restrict__ Wkr,
                       const float* __restrict__ Wo) {
    int z = blockIdx.z;
    const float* W = (z == 0) ? Wq : (z == 1) ? Wke : (z == 2) ? Wv : (z == 3) ? Wkr : Wo;
    __nv_bfloat16* hi = g_WThi + (size_t)z * D_ * D_;
    __nv_bfloat16* lo = g_WTlo + (size_t)z * D_ * D_;
    __shared__ float tbuf[32][33];
    int tx = threadIdx.x & 31, ty = threadIdx.x >> 5;
    int nn0 = blockIdx.x * 32, kk0 = blockIdx.y * 32;
#pragma unroll
    for (int i = 0; i < 4; i++)
        tbuf[ty * 4 + i][tx] = W[(size_t)(kk0 + ty * 4 + i) * D_ + nn0 + tx];
    __syncthreads();
#pragma unroll
    for (int i = 0; i < 4; i++) {
        float v = tbuf[tx][ty * 4 + i];
        __nv_bfloat16 h, l;
        split_bf16(v, h, l);
        size_t off = (size_t)(nn0 + ty * 4 + i) * D_ + kk0 + tx;
        hi[off] = h;
        lo[off] = l;
    }
}

// =================================================================
// Pre-pass 3 (after attention): gather g_O head-layout -> row-major hi/lo
// =================================================================
__global__ __launch_bounds__(256)
void o_convert_kernel() {
    int i = blockIdx.x * 256 + threadIdx.x;
    float4 v = ((const float4*)g_O)[i];
    int idx = i * 4;
    int d = idx & 63;
    int rest = idx >> 6;
    int ir = rest & 1023;
    int bh = rest >> 10;
    int bb = bh >> 4, hh = bh & 15;
    size_t off = ((size_t)(bb * 1024 + ir) * D_ + hh * 64 + d);
    __nv_bfloat16 hx, lx, hy, ly, hz, lz, hw, lw;
    split_bf16(v.x, hx, lx); split_bf16(v.y, hy, ly);
    split_bf16(v.z, hz, lz); split_bf16(v.w, hw, lw);
    __nv_bfloat162 h0; h0.x = hx; h0.y = hy;
    __nv_bfloat162 h1; h1.x = hz; h1.y = hw;
    __nv_bfloat162 l0; l0.x = lx; l0.y = ly;
    __nv_bfloat162 l1; l1.x = lz; l1.y = lw;
    *(__nv_bfloat162*)(g_Ohi + off)     = h0;
    *(__nv_bfloat162*)(g_Ohi + off + 2) = h1;
    *(__nv_bfloat162*)(g_Olo + off)     = l0;
    *(__nv_bfloat162*)(g_Olo + off + 2) = l1;
}

// =================================================================
// Split-bf16 GEMM via mma.sync. phase 0: q/k/v/Qr -> fp16 hi/lo head
// layout (q gets +cb). phase 1: oproj -> g_res (+Ev+Wo_b).
// =================================================================
#define KC 32
#define SROW 80
#define MAT_BYTES (128 * SROW)
#define STAGE_BYTES (4 * MAT_BYTES)
#define GEMM_SMEM (2 * STAGE_BYTES)

__global__ __launch_bounds__(256)
void mma_gemm_kernel(int phase, const float* __restrict__ Ev,
                     const float* __restrict__ Wo_b,
                     const float* __restrict__ cbv) {
    extern __shared__ __align__(16) char sm[];
    int tid = threadIdx.x;
    int lane = tid & 31, wid = tid >> 5;

    int t = blockIdx.x;
    const __nv_bfloat16 *Ahi, *Alo;
    int row0, col0, which;
    if (phase == 0) {
        if (t < 384) {
            which = t >> 7;
            int loc = t & 127;
            row0 = (loc >> 3) * 128;
            col0 = (loc & 7) * 128;
            if (which == 0) { Ahi = g_Ehi;  Alo = g_Elo;  }
            else            { Ahi = g_Evhi; Alo = g_Evlo; }
        } else {
            which = 3;
            int loc = t - 384;
            row0 = (loc >> 3) * 128;
            col0 = (loc & 7) * 128;
            Ahi = g_Rhi; Alo = g_Rlo;
        }
    } else {
        which = 4;
        row0 = (t >> 3) * 128;
        col0 = (t & 7) * 128;
        Ahi = g_Ohi; Alo = g_Olo;
    }
    const __nv_bfloat16* Bhi = g_WThi + (size_t)which * D_ * D_;
    const __nv_bfloat16* Blo = g_WTlo + (size_t)which * D_ * D_;

    const int wm = (wid >> 2) * 64;
    const int wn = (wid & 3) * 32;

    float c[4][4][4];
#pragma unroll
    for (int a = 0; a < 4; a++)
#pragma unroll
        for (int b = 0; b < 4; b++)
#pragma unroll
            for (int e = 0; e < 4; e++) c[a][b][e] = 0.f;

    uint4 pr[8];
    {
#pragma unroll
        for (int l = 0; l < 2; l++) {
            int idx = tid + 256 * l;
            int row = idx >> 2, colc = (idx & 3) * 8;
            size_t ga = (size_t)(row0 + row) * D_ + colc;
            size_t gb = (size_t)(col0 + row) * D_ + colc;
            pr[l * 4 + 0] = *(const uint4*)(Ahi + ga);
            pr[l * 4 + 1] = *(const uint4*)(Alo + ga);
            pr[l * 4 + 2] = *(const uint4*)(Bhi + gb);
            pr[l * 4 + 3] = *(const uint4*)(Blo + gb);
        }
        char* base = sm;
#pragma unroll
        for (int l = 0; l < 2; l++) {
            int idx = tid + 256 * l;
            int row = idx >> 2, colc = (idx & 3) * 8;
            int so = row * SROW + colc * 2;
            *(uint4*)(base + so)                 = pr[l * 4 + 0];
            *(uint4*)(base + MAT_BYTES + so)     = pr[l * 4 + 1];
            *(uint4*)(base + 2 * MAT_BYTES + so) = pr[l * 4 + 2];
            *(uint4*)(base + 3 * MAT_BYTES + so) = pr[l * 4 + 3];
        }
    }
    __syncthreads();

    for (int ch = 0; ch < D_ / KC; ch++) {
        if (ch + 1 < D_ / KC) {
            int kc0 = (ch + 1) * KC;
#pragma unroll
            for (int l = 0; l < 2; l++) {
                int idx = tid + 256 * l;
                int row = idx >> 2, colc = (idx & 3) * 8;
                size_t ga = (size_t)(row0 + row) * D_ + kc0 + colc;
                size_t gb = (size_t)(col0 + row) * D_ + kc0 + colc;
                pr[l * 4 + 0] = *(const uint4*)(Ahi + ga);
                pr[l * 4 + 1] = *(const uint4*)(Alo + ga);
                pr[l * 4 + 2] = *(const uint4*)(Bhi + gb);
                pr[l * 4 + 3] = *(const uint4*)(Blo + gb);
            }
        }
        {
            const char* base = sm + (ch & 1) * STAGE_BYTES;
#pragma unroll
            for (int ks = 0; ks < 2; ks++) {
                int kb = ks * 32;
                unsigned bh[4][2], bl[4][2];
#pragma unroll
                for (int nt = 0; nt < 4; nt++) {
                    const char* bp = base + 2 * MAT_BYTES +
                        (wn + nt * 8 + (lane >> 2)) * SROW + kb + (lane & 3) * 4;
                    bh[nt][0] = *(const unsigned*)bp;
                    bh[nt][1] = *(const unsigned*)(bp + 16);
                    bl[nt][0] = *(const unsigned*)(bp + MAT_BYTES);
                    bl[nt][1] = *(const unsigned*)(bp + MAT_BYTES + 16);
                }
#pragma unroll
                for (int mt = 0; mt < 4; mt++) {
                    const char* ap = base +
                        (wm + mt * 16 + (lane >> 2)) * SROW + kb + (lane & 3) * 4;
                    unsigned a0 = *(const unsigned*)ap;
                    unsigned a1 = *(const unsigned*)(ap + 8 * SROW);
                    unsigned a2 = *(const unsigned*)(ap + 16);
                    unsigned a3 = *(const unsigned*)(ap + 8 * SROW + 16);
                    unsigned l0 = *(const unsigned*)(ap + MAT_BYTES);
                    unsigned l1 = *(const unsigned*)(ap + MAT_BYTES + 8 * SROW);
                    unsigned l2 = *(const unsigned*)(ap + MAT_BYTES + 16);
                    unsigned l3 = *(const unsigned*)(ap + MAT_BYTES + 8 * SROW + 16);
#pragma unroll
                    for (int nt = 0; nt < 4; nt++) {
                        mma_bf16(c[mt][nt], a0, a1, a2, a3, bh[nt][0], bh[nt][1]);
                        mma_bf16(c[mt][nt], l0, l1, l2, l3, bh[nt][0], bh[nt][1]);
                        mma_bf16(c[mt][nt], a0, a1, a2, a3, bl[nt][0], bl[nt][1]);
                    }
                }
            }
        }
        if (ch + 1 < D_ / KC) {
            char* base = sm + ((ch + 1) & 1) * STAGE_BYTES;
#pragma unroll
            for (int l = 0; l < 2; l++) {
                int idx = tid + 256 * l;
                int row = idx >> 2, colc = (idx & 3) * 8;
                int so = row * SROW + colc * 2;
                *(uint4*)(base + so)                 = pr[l * 4 + 0];
                *(uint4*)(base + MAT_BYTES + so)     = pr[l * 4 + 1];
                *(uint4*)(base + 2 * MAT_BYTES + so) = pr[l * 4 + 2];
                *(uint4*)(base + 3 * MAT_BYTES + so) = pr[l * 4 + 3];
            }
        }
        __syncthreads();
    }

    // ---- epilogue ----
#pragma unroll
    for (int mt = 0; mt < 4; mt++) {
#pragma unroll
        for (int nt = 0; nt < 4; nt++) {
            int r   = row0 + wm + mt * 16 + (lane >> 2);
            int col = col0 + wn + nt * 8 + (lane & 3) * 2;
            if (phase == 0) {
                float v00 = c[mt][nt][0], v01 = c[mt][nt][1];
                float v10 = c[mt][nt][2], v11 = c[mt][nt][3];
                if (which == 0) {
                    float cb0 = cbv[col], cb1 = cbv[col + 1];
                    v00 += cb0; v01 += cb1; v10 += cb0; v11 += cb1;
                }
                int hh = col >> 6, d = col & 63;
                __half *dh, *dl;
                size_t off0, off1;
                if (which == 3) {
                    dh = g_Qrh; dl = g_Qrl;
                    off0 = ((size_t)(hh * L_ + r)) * DH + d;
                    off1 = ((size_t)(hh * L_ + r + 8)) * DH + d;
                } else {
                    dh = (which == 0) ? g_qch : (which == 1) ? g_kh : g_vh;
                    dl = (which == 0) ? g_qcl : (which == 1) ? g_kl : g_vl;
                    int bb = r >> 10, ir = r & 1023;
                    off0 = ((size_t)((bb * H_ + hh) * L_ + ir)) * DH + d;
                    off1 = off0 + 8 * DH;
                }
                __half h00 = __float2half(v00), h01 = __float2half(v01);
                __half h10 = __float2half(v10), h11 = __float2half(v11);
                __half l00 = __float2half(v00 - __half2float(h00));
                __half l01 = __float2half(v01 - __half2float(h01));
                __half l10 = __float2half(v10 - __half2float(h10));
                __half l11 = __float2half(v11 - __half2float(h11));
                __half2 p;
                p.x = h00; p.y = h01; *(__half2*)(dh + off0) = p;
                p.x = l00; p.y = l01; *(__half2*)(dl + off0) = p;
                p.x = h10; p.y = h11; *(__half2*)(dh + off1) = p;
                p.x = l10; p.y = l11; *(__half2*)(dl + off1) = p;
            } else {
                float2 wb = *(const float2*)(Wo_b + col);
                float2 e0 = *(const float2*)(Ev + (size_t)r * D_ + col);
                float2 e1 = *(const float2*)(Ev + (size_t)(r + 8) * D_ + col);
                float2 o0 = make_float2(c[mt][nt][0] + wb.x + e0.x, c[mt][nt][1] + wb.y + e0.y);
                float2 o1 = make_float2(c[mt][nt][2] + wb.x + e1.x, c[mt][nt][3] + wb.y + e1.y);
                *(float2*)(g_res + (size_t)r * D_ + col) = o0;
                *(float2*)(g_res + (size_t)(r + 8) * D_ + col) = o1;
            }
        }
    }
}

// =================================================================
// mma attention. CTA: 64 query rows of one (b,h), 4 warps, warp = 16
// full rows. S = qc.k (3-pass fp16) + [qc.Qr_band + r(t)] (pos tiles),
// online softmax (warp-local), O += P.V (3-pass fp16).
// =================================================================
#define HSTRIDE 72                      // halves per smem row (144 B)
#define T64  (64 * HSTRIDE * 2)         // 9216 B
#define T128 (128 * HSTRIDE * 2)        // 18432 B
#define OFF_QCH 0
#define OFF_QCL (OFF_QCH + T64)
#define OFF_KH  (OFF_QCL + T64)
#define OFF_KL  (OFF_KH + T64)
#define OFF_VH  (OFF_KL + T64)
#define OFF_VL  (OFF_VH + T64)
#define OFF_QRH (OFF_VL + T64)
#define OFF_QRL (OFF_QRH + T128)
#define OFF_SPOS (OFF_QRL + T128)       // float [64][65]
#define OFF_R    (OFF_SPOS + 64 * 65 * 4)
#define OFF_DELTA (OFF_R + 128 * 4)
#define ATTN_SMEM (OFF_DELTA + 64 * 4)

__global__ __launch_bounds__(128)
void attn_mma_kernel(const float* __restrict__ cbv, const float* __restrict__ pbv) {
    extern __shared__ __align__(16) char sm[];
    unsigned sbase = smem_u32(sm);
    int tid = threadIdx.x, lane = tid & 31, w = tid >> 5;
    int ib = blockIdx.x, bh = blockIdx.y, h = bh & 15;
    int i0 = ib * 64;

    const __half* qch_g = g_qch + (size_t)bh * L_ * DH;
    const __half* qcl_g = g_qcl + (size_t)bh * L_ * DH;
    const __half* kh_g  = g_kh  + (size_t)bh * L_ * DH;
    const __half* kl_g  = g_kl  + (size_t)bh * L_ * DH;
    const __half* vh_g  = g_vh  + (size_t)bh * L_ * DH;
    const __half* vl_g  = g_vl  + (size_t)bh * L_ * DH;
    const __half* Qrh_g = g_Qrh + (size_t)h * L_ * DH;
    const __half* Qrl_g = g_Qrl + (size_t)h * L_ * DH;

    float* Spos  = (float*)(sm + OFF_SPOS);
    float* r_s   = (float*)(sm + OFF_R);
    float* delta = (float*)(sm + OFF_DELTA);

    if (tid < 64) delta[tid] = pbv[h * DH + tid] - cbv[h * DH + tid];

    // load qc tile (64 x 64 hi/lo)
#pragma unroll
    for (int it = 0; it < 4; it++) {
        int idx = tid + 128 * it;
        int row = idx >> 3, dc = (idx & 7) * 8;
        size_t go = (size_t)(i0 + row) * DH + dc;
        *(uint4*)(sm + OFF_QCH + row * 144 + dc * 2) = *(const uint4*)(qch_g + go);
        *(uint4*)(sm + OFF_QCL + row * 144 + dc * 2) = *(const uint4*)(qcl_g + go);
    }
    __syncthreads();

    // resident A-fragments of qc (rows 16w..16w+15)
    unsigned aqh[4][4], aql[4][4];
#pragma unroll
    for (int kk = 0; kk < 4; kk++) {
        unsigned ao = ((16 * w + (lane & 15)) * HSTRIDE + kk * 16 + (lane >> 4) * 8) * 2;
        ldsm_x4(aqh[kk][0], aqh[kk][1], aqh[kk][2], aqh[kk][3], sbase + OFF_QCH + ao);
        ldsm_x4(aql[kk][0], aql[kk][1], aql[kk][2], aql[kk][3], sbase + OFF_QCL + ao);
    }

    float O[8][4];
#pragma unroll
    for (int dn = 0; dn < 8; dn++)
#pragma unroll
        for (int e = 0; e < 4; e++) O[dn][e] = 0.f;
    float m_a = -1e30f, m_b = -1e30f, l_a = 0.f, l_b = 0.f;
    const int ra = lane >> 2;                 // 0..7
    const int il_a = 16 * w + ra, il_b = il_a + 8;

    for (int jt = 0; jt < 16; jt++) {
        int j0 = jt * 64;
        bool pos = (jt <= ib);
        __syncthreads();
        // load k, v hi/lo
#pragma unroll
        for (int it = 0; it < 4; it++) {
            int idx = tid + 128 * it;
            int row = idx >> 3, dc = (idx & 7) * 8;
            size_t go = (size_t)(j0 + row) * DH + dc;
            int so = row * 144 + dc * 2;
            *(uint4*)(sm + OFF_KH + so) = *(const uint4*)(kh_g + go);
            *(uint4*)(sm + OFF_KL + so) = *(const uint4*)(kl_g + go);
            *(uint4*)(sm + OFF_VH + so) = *(const uint4*)(vh_g + go);
            *(uint4*)(sm + OFF_VL + so) = *(const uint4*)(vl_g + go);
        }
        int c0 = L_ - 64 - i0 + j0;
        if (pos) {
#pragma unroll
            for (int it = 0; it < 8; it++) {
                int idx = tid + 128 * it;
                int row = idx >> 3, dc = (idx & 7) * 8;
                int m = c0 + row;
                uint4 zh = make_uint4(0, 0, 0, 0), zl = make_uint4(0, 0, 0, 0);
                if (m < L_) {
                    size_t go = (size_t)m * DH + dc;
                    zh = *(const uint4*)(Qrh_g + go);
                    zl = *(const uint4*)(Qrl_g + go);
                }
                int so = row * 144 + dc * 2;
                *(uint4*)(sm + OFF_QRH + so) = zh;
                *(uint4*)(sm + OFF_QRL + so) = zl;
            }
        }
        __syncthreads();
        if (pos) {
            // r[t] = delta . Qr[t]
            const __half* qh = (const __half*)(sm + OFF_QRH) + tid * HSTRIDE;
            const __half* ql = (const __half*)(sm + OFF_QRL) + tid * HSTRIDE;
            float acc = 0.f;
#pragma unroll 16
            for (int d = 0; d < 64; d++)
                acc += delta[d] * (__half2float(qh[d]) + __half2float(ql[d]));
            r_s[tid] = acc;
        }
        __syncthreads();

        if (pos) {
            // G = qc @ Qr_band^T, scattered pre-shifted into Spos
#pragma unroll
            for (int half = 0; half < 2; half++) {
                float g[8][4];
#pragma unroll
                for (int tn = 0; tn < 8; tn++)
#pragma unroll
                    for (int e = 0; e < 4; e++) g[tn][e] = 0.f;
#pragma unroll
                for (int kk = 0; kk < 4; kk++) {
#pragma unroll
                    for (int tp = 0; tp < 4; tp++) {
                        unsigned b0, b1, b2, b3;
                        unsigned bo = (((half * 8 + 2 * tp + (lane >> 4)) * 8 + (lane & 7)) * HSTRIDE
                                       + kk * 16 + ((lane >> 3) & 1) * 8) * 2;
                        ldsm_x4(b0, b1, b2, b3, sbase + OFF_QRH + bo);
                        mma_f16(g[2 * tp],     aqh[kk][0], aqh[kk][1], aqh[kk][2], aqh[kk][3], b0, b1);
                        mma_f16(g[2 * tp + 1], aqh[kk][0], aqh[kk][1], aqh[kk][2], aqh[kk][3], b2, b3);
                        mma_f16(g[2 * tp],     aql[kk][0], aql[kk][1], aql[kk][2], aql[kk][3], b0, b1);
                        mma_f16(g[2 * tp + 1], aql[kk][0], aql[kk][1], aql[kk][2], aql[kk][3], b2, b3);
                        ldsm_x4(b0, b1, b2, b3, sbase + OFF_QRL + bo);
                        mma_f16(g[2 * tp],     aqh[kk][0], aqh[kk][1], aqh[kk][2], aqh[kk][3], b0, b1);
                        mma_f16(g[2 * tp + 1], aqh[kk][0], aqh[kk][1], aqh[kk][2], aqh[kk][3], b2, b3);
                    }
                }
#pragma unroll
                for (int tn = 0; tn < 8; tn++) {
                    int tbase = half * 64 + tn * 8 + (lane & 3) * 2;
#pragma unroll
                    for (int e = 0; e < 2; e++) {
                        int tt = tbase + e;
                        float rv = r_s[tt];
                        int ja = tt + il_a - 63;
                        if (ja >= 0 && ja < 64) Spos[il_a * 65 + ja] = g[tn][e] + rv;
                        int jb = tt + il_b - 63;
                        if (jb >= 0 && jb < 64) Spos[il_b * 65 + jb] = g[tn][2 + e] + rv;
                    }
                }
            }
            __syncwarp();
        }

        // content scores
        float s[8][4];
#pragma unroll
        for (int jn = 0; jn < 8; jn++)
#pragma unroll
            for (int e = 0; e < 4; e++) s[jn][e] = 0.f;
#pragma unroll
        for (int kk = 0; kk < 4; kk++) {
#pragma unroll
            for (int jp = 0; jp < 4; jp++) {
                unsigned b0, b1, b2, b3;
                unsigned bo = (((2 * jp + (lane >> 4)) * 8 + (lane & 7)) * HSTRIDE
                               + kk * 16 + ((lane >> 3) & 1) * 8) * 2;
                ldsm_x4(b0, b1, b2, b3, sbase + OFF_KH + bo);
                mma_f16(s[2 * jp],     aqh[kk][0], aqh[kk][1], aqh[kk][2], aqh[kk][3], b0, b1);
                mma_f16(s[2 * jp + 1], aqh[kk][0], aqh[kk][1], aqh[kk][2], aqh[kk][3], b2, b3);
                mma_f16(s[2 * jp],     aql[kk][0], aql[kk][1], aql[kk][2], aql[kk][3], b0, b1);
                mma_f16(s[2 * jp + 1], aql[kk][0], aql[kk][1], aql[kk][2], aql[kk][3], b2, b3);
                ldsm_x4(b0, b1, b2, b3, sbase + OFF_KL + bo);
                mma_f16(s[2 * jp],     aqh[kk][0], aqh[kk][1], aqh[kk][2], aqh[kk][3], b0, b1);
                mma_f16(s[2 * jp + 1], aqh[kk][0], aqh[kk][1], aqh[kk][2], aqh[kk][3], b2, b3);
            }
        }
        if (pos) {
#pragma unroll
            for (int jn = 0; jn < 8; jn++) {
                int jc = jn * 8 + (lane & 3) * 2;
                s[jn][0] += Spos[il_a * 65 + jc];
                s[jn][1] += Spos[il_a * 65 + jc + 1];
                s[jn][2] += Spos[il_b * 65 + jc];
                s[jn][3] += Spos[il_b * 65 + jc + 1];
            }
        }

        // online softmax (warp-local)
        float mta = -1e30f, mtb = -1e30f;
#pragma unroll
        for (int jn = 0; jn < 8; jn++) {
            mta = fmaxf(mta, fmaxf(s[jn][0], s[jn][1]));
            mtb = fmaxf(mtb, fmaxf(s[jn][2], s[jn][3]));
        }
        mta = fmaxf(mta, __shfl_xor_sync(0xffffffffu, mta, 1));
        mta = fmaxf(mta, __shfl_xor_sync(0xffffffffu, mta, 2));
        mtb = fmaxf(mtb, __shfl_xor_sync(0xffffffffu, mtb, 1));
        mtb = fmaxf(mtb, __shfl_xor_sync(0xffffffffu, mtb, 2));
        float mna = fmaxf(m_a, mta), mnb = fmaxf(m_b, mtb);
        float sca = __expf(m_a - mna), scb = __expf(m_b - mnb);
        m_a = mna; m_b = mnb;
        float suma = 0.f, sumb = 0.f;
        float p[8][4];
#pragma unroll
        for (int jn = 0; jn < 8; jn++) {
            p[jn][0] = __expf(s[jn][0] - mna);
            p[jn][1] = __expf(s[jn][1] - mna);
            p[jn][2] = __expf(s[jn][2] - mnb);
            p[jn][3] = __expf(s[jn][3] - mnb);
            suma += p[jn][0] + p[jn][1];
            sumb += p[jn][2] + p[jn][3];
        }
        suma += __shfl_xor_sync(0xffffffffu, suma, 1);
        suma += __shfl_xor_sync(0xffffffffu, suma, 2);
        sumb += __shfl_xor_sync(0xffffffffu, sumb, 1);
        sumb += __shfl_xor_sync(0xffffffffu, sumb, 2);
        l_a = l_a * sca + suma;
        l_b = l_b * scb + sumb;
#pragma unroll
        for (int dn = 0; dn < 8; dn++) {
            O[dn][0] *= sca; O[dn][1] *= sca;
            O[dn][2] *= scb; O[dn][3] *= scb;
        }

        // O += P @ V  (3-pass split, A-frags in-register)
#pragma unroll
        for (int kj = 0; kj < 4; kj++) {
            __half h00 = __float2half(p[2 * kj][0]),     h01 = __float2half(p[2 * kj][1]);
            __half h02 = __float2half(p[2 * kj][2]),     h03 = __float2half(p[2 * kj][3]);
            __half h10 = __float2half(p[2 * kj + 1][0]), h11 = __float2half(p[2 * kj + 1][1]);
            __half h12 = __float2half(p[2 * kj + 1][2]), h13 = __float2half(p[2 * kj + 1][3]);
            unsigned pa0 = pack_h2(h00, h01), pa1 = pack_h2(h02, h03);
            unsigned pa2 = pack_h2(h10, h11), pa3 = pack_h2(h12, h13);
            unsigned pl0 = pack_h2(__float2half(p[2 * kj][0] - __half2float(h00)),
                                   __float2half(p[2 * kj][1] - __half2float(h01)));
            unsigned pl1 = pack_h2(__float2half(p[2 * kj][2] - __half2float(h02)),
                                   __float2half(p[2 * kj][3] - __half2float(h03)));
            unsigned pl2 = pack_h2(__float2half(p[2 * kj + 1][0] - __half2float(h10)),
                                   __float2half(p[2 * kj + 1][1] - __half2float(h11)));
            unsigned pl3 = pack_h2(__float2half(p[2 * kj + 1][2] - __half2float(h12)),
                                   __float2half(p[2 * kj + 1][3] - __half2float(h13)));
#pragma unroll
            for (int dp = 0; dp < 4; dp++) {
                unsigned v0, v1, v2, v3;
                unsigned bo = ((kj * 16 + ((lane >> 3) & 1) * 8 + (lane & 7)) * HSTRIDE
                               + (2 * dp + (lane >> 4)) * 8) * 2;
                ldsm_x4_t(v0, v1, v2, v3, sbase + OFF_VH + bo);
                mma_f16(O[2 * dp],     pa0, pa1, pa2, pa3, v0, v1);
                mma_f16(O[2 * dp + 1], pa0, pa1, pa2, pa3, v2, v3);
                mma_f16(O[2 * dp],     pl0, pl1, pl2, pl3, v0, v1);
                mma_f16(O[2 * dp + 1], pl0, pl1, pl2, pl3, v2, v3);
                ldsm_x4_t(v0, v1, v2, v3, sbase + OFF_VL + bo);
                mma_f16(O[2 * dp],     pa0, pa1, pa2, pa3, v0, v1);
                mma_f16(O[2 * dp + 1], pa0, pa1, pa2, pa3, v2, v3);
            }
        }
    }

    // normalize + store
    float inva = 1.f / l_a, invb = 1.f / l_b;
    int ga = i0 + il_a, gb = i0 + il_b;
#pragma unroll
    for (int dn = 0; dn < 8; dn++) {
        int d = dn * 8 + (lane & 3) * 2;
        float2 oa = make_float2(O[dn][0] * inva, O[dn][1] * inva);
        float2 ob = make_float2(O[dn][2] * invb, O[dn][3] * invb);
        *(float2*)(g_O + ((size_t)(bh * L_ + ga)) * DH + d) = oa;
        *(float2*)(g_O + ((size_t)(bh * L_ + gb)) * DH + d) = ob;
    }
}

// =================================================================
// LayerNorm (unchanged).
// =================================================================
__global__ __launch_bounds__(256)
void ln_kernel(const float* __restrict__ gamma,
               const float* __restrict__ beta,
               float* __restrict__ out) {
    int row = blockIdx.x;
    int tid = threadIdx.x;
    const float* x = g_res + (size_t)row * D_;
    float4 v = *(const float4*)(x + tid * 4);
    float s  = v.x + v.y + v.z + v.w;
    float ss = v.x * v.x + v.y * v.y + v.z * v.z + v.w * v.w;
#pragma unroll
    for (int off = 16; off > 0; off >>= 1) {
        s  += __shfl_down_sync(0xffffffffu, s,  off);
        ss += __shfl_down_sync(0xffffffffu, ss, off);
    }
    __shared__ float sbuf[8], ssbuf[8];
    __shared__ float mu_s, inv_s;
    int w = tid >> 5;
    if ((tid & 31) == 0) { sbuf[w] = s; ssbuf[w] = ss; }
    __syncthreads();
    if (tid == 0) {
        float st = 0.f, sst = 0.f;
#pragma unroll
        for (int i = 0; i < 8; i++) { st += sbuf[i]; sst += ssbuf[i]; }
        float mu = st * (1.0f / D_);
        float var = sst * (1.0f / D_) - mu * mu;
        mu_s = mu;
        inv_s = rsqrtf(var + 1e-5f);
    }
    __syncthreads();
    float mu = mu_s, inv = inv_s;
    float4 g4 = *(const float4*)(gamma + tid * 4);
    float4 b4 = *(const float4*)(beta + tid * 4);
    float4 o4;
    o4.x = (v.x - mu) * inv * g4.x + b4.x;
    o4.y = (v.y - mu) * inv * g4.y + b4.y;
    o4.z = (v.z - mu) * inv * g4.z + b4.z;
    o4.w = (v.w - mu) * inv * g4.w + b4.w;
    *(float4*)(out + (size_t)row * D_ + tid * 4) = o4;
}

// =================================================================
extern "C" void kernel_launch(void* const* d_in, const int* in_sizes, int n_in,
                              void* d_out, int out_size) {
    const float* E    = (const float*)d_in[0];
    const float* Ev   = (const float*)d_in[1];
    const float* R    = (const float*)d_in[2];
    const float* Wq   = (const float*)d_in[3];
    const float* Wke  = (const float*)d_in[4];
    const float* Wkr  = (const float*)d_in[5];
    const float* Wv   = (const float*)d_in[6];
    const float* cb   = (const float*)d_in[7];
    const float* pb   = (const float*)d_in[8];
    const float* Wo_w = (const float*)d_in[9];
    const float* Wo_b = (const float*)d_in[10];
    const float* ln_g = (const float*)d_in[11];
    const float* ln_b = (const float*)d_in[12];
    float* out = (float*)d_out;

    cudaFuncSetAttribute(mma_gemm_kernel, cudaFuncAttributeMaxDynamicSharedMemorySize,
                         GEMM_SMEM);
    cudaFuncSetAttribute(attn_mma_kernel, cudaFuncAttributeMaxDynamicSharedMemorySize,
                         ATTN_SMEM);

    dim3 sg(B_ * L_ * D_ / 4 / 256, 1, 3);
    split_convert_kernel<<<sg, 256>>>(E, Ev, R);
    dim3 wg(D_ / 32, D_ / 32, 5);
    wt_convert_kernel<<<wg, 256>>>(Wq, Wke, Wv, Wkr, Wo_w);

    mma_gemm_kernel<<<448, 256, GEMM_SMEM>>>(0, Ev, Wo_b, cb);

    dim3 ag(L_ / 64, B_ * H_);
    attn_mma_kernel<<<ag, 128, ATTN_SMEM>>>(cb, pb);

    o_convert_kernel<<<B_ * L_ * D_ / 4 / 256, 256>>>();
    mma_gemm_kernel<<<128, 256, GEMM_SMEM>>>(1, Ev, Wo_b, cb);

    ln_kernel<<<B_ * L_, 256>>>(ln_g, ln_b, out);
}

// round 13
// speedup vs baseline: 2.2164x; 1.0095x over previous
#include <cuda_runtime.h>
#include <cuda_bf16.h>
#include <cuda_fp16.h>

#define B_ 2
#define L_ 1024
#define D_ 1024
#define H_ 16
#define DH 64

// ---------------- scratch (no cudaMalloc allowed) ----------------
__device__ float g_res[B_*L_*D_];       // residual before LN

// bf16 hi/lo split operands for projection GEMMs
__device__ __nv_bfloat16 g_Ehi [B_*L_*D_], g_Elo [B_*L_*D_];
__device__ __nv_bfloat16 g_Evhi[B_*L_*D_], g_Evlo[B_*L_*D_];
__device__ __nv_bfloat16 g_Rhi [L_*D_],    g_Rlo [L_*D_];
__device__ __nv_bfloat16 g_WThi[5*D_*D_],  g_WTlo[5*D_*D_];   // transposed [N][K]
__device__ __nv_bfloat16 g_Ohi [B_*L_*D_], g_Olo [B_*L_*D_];  // attn out, row-major hi/lo

// fp16 hi/lo operands for mma attention (head layout [b][h][i][d])
__device__ __half g_qch[B_*H_*L_*DH], g_qcl[B_*H_*L_*DH];   // q + cb
__device__ __half g_kh [B_*H_*L_*DH], g_kl [B_*H_*L_*DH];
__device__ __half g_vh [B_*H_*L_*DH], g_vl [B_*H_*L_*DH];
__device__ __half g_Qrh[H_*L_*DH],    g_Qrl[H_*L_*DH];      // [h][m][d]

__device__ __forceinline__ void split_bf16(float x, __nv_bfloat16& hi, __nv_bfloat16& lo) {
    hi = __float2bfloat16(x);
    lo = __float2bfloat16(x - __bfloat162float(hi));
}
__device__ __forceinline__ unsigned smem_u32(const void* p) {
    unsigned a;
    asm("{ .reg .u64 t; cvta.to.shared.u64 t, %1; cvt.u32.u64 %0, t; }" : "=r"(a) : "l"(p));
    return a;
}
__device__ __forceinline__ void mma_bf16(float* c,
                                         unsigned a0, unsigned a1, unsigned a2, unsigned a3,
                                         unsigned b0, unsigned b1) {
    asm volatile(
        "mma.sync.aligned.m16n8k16.row.col.f32.bf16.bf16.f32 "
        "{%0,%1,%2,%3}, {%4,%5,%6,%7}, {%8,%9}, {%0,%1,%2,%3};"
        : "+f"(c[0]), "+f"(c[1]), "+f"(c[2]), "+f"(c[3])
        : "r"(a0), "r"(a1), "r"(a2), "r"(a3), "r"(b0), "r"(b1));
}
__device__ __forceinline__ void mma_f16(float* c,
                                        unsigned a0, unsigned a1, unsigned a2, unsigned a3,
                                        unsigned b0, unsigned b1) {
    asm volatile(
        "mma.sync.aligned.m16n8k16.row.col.f32.f16.f16.f32 "
        "{%0,%1,%2,%3}, {%4,%5,%6,%7}, {%8,%9}, {%0,%1,%2,%3};"
        : "+f"(c[0]), "+f"(c[1]), "+f"(c[2]), "+f"(c[3])
        : "r"(a0), "r"(a1), "r"(a2), "r"(a3), "r"(b0), "r"(b1));
}
__device__ __forceinline__ void ldsm_x4(unsigned& r0, unsigned& r1, unsigned& r2, unsigned& r3,
                                        unsigned addr) {
    asm volatile("ldmatrix.sync.aligned.m8n8.x4.shared.b16 {%0,%1,%2,%3}, [%4];"
                 : "=r"(r0), "=r"(r1), "=r"(r2), "=r"(r3) : "r"(addr));
}
__device__ __forceinline__ void ldsm_x4_t(unsigned& r0, unsigned& r1, unsigned& r2, unsigned& r3,
                                          unsigned addr) {
    asm volatile("ldmatrix.sync.aligned.m8n8.x4.trans.shared.b16 {%0,%1,%2,%3}, [%4];"
                 : "=r"(r0), "=r"(r1), "=r"(r2), "=r"(r3) : "r"(addr));
}
__device__ __forceinline__ unsigned pack_h2(__half a, __half b) {
    __half2 h; h.x = a; h.y = b;
    return *reinterpret_cast<unsigned*>(&h);
}

// =================================================================
// Pre-pass 1: split-convert activations E, Ev, R -> hi/lo bf16
// =================================================================
__global__ __launch_bounds__(256)
void split_convert_kernel(const float* __restrict__ E,
                          const float* __restrict__ Ev,
                          const float* __restrict__ R) {
    int z = blockIdx.z;
    const float* src = (z == 0) ? E : (z == 1) ? Ev : R;
    __nv_bfloat16* hi = (z == 0) ? g_Ehi : (z == 1) ? g_Evhi : g_Rhi;
    __nv_bfloat16* lo = (z == 0) ? g_Elo : (z == 1) ? g_Evlo : g_Rlo;
    int n4 = (z == 2) ? (L_ * D_ / 4) : (B_ * L_ * D_ / 4);
    int i = blockIdx.x * 256 + threadIdx.x;
    if (i >= n4) return;
    float4 v = ((const float4*)src)[i];
    __nv_bfloat16 hx, lx, hy, ly, hz, lz, hw, lw;
    split_bf16(v.x, hx, lx); split_bf16(v.y, hy, ly);
    split_bf16(v.z, hz, lz); split_bf16(v.w, hw, lw);
    __nv_bfloat162 h0; h0.x = hx; h0.y = hy;
    __nv_bfloat162 h1; h1.x = hz; h1.y = hw;
    __nv_bfloat162 l0; l0.x = lx; l0.y = ly;
    __nv_bfloat162 l1; l1.x = lz; l1.y = lw;
    ((__nv_bfloat162*)hi)[2 * i]     = h0;
    ((__nv_bfloat162*)hi)[2 * i + 1] = h1;
    ((__nv_bfloat162*)lo)[2 * i]     = l0;
    ((__nv_bfloat162*)lo)[2 * i + 1] = l1;
}

// =================================================================
// Pre-pass 2: transpose + split-convert weights [K][N] -> [N][K] hi/lo
// =================================================================
__global__ __launch_bounds__(256)
void wt_convert_kernel(const float* __restrict__ Wq, const float* __restrict__ Wke,
                       const float* __restrict__ Wv, const float* __restrict__ Wkr,
                       const float* __restrict__ Wo) {
    int z = blockIdx.z;
    const float* W = (z == 0) ? Wq : (z == 1) ? Wke : (z == 2) ? Wv : (z == 3) ? Wkr : Wo;
    __nv_bfloat16* hi = g_WThi + (size_t)z * D_ * D_;
    __nv_bfloat16* lo = g_WTlo + (size_t)z * D_ * D_;
    __shared__ float tbuf[32][33];
    int tx = threadIdx.x & 31, ty = threadIdx.x >> 5;
    int nn0 = blockIdx.x * 32, kk0 = blockIdx.y * 32;
#pragma unroll
    for (int i = 0; i < 4; i++)
        tbuf[ty * 4 + i][tx] = W[(size_t)(kk0 + ty * 4 + i) * D_ + nn0 + tx];
    __syncthreads();
#pragma unroll
    for (int i = 0; i < 4; i++) {
        float v = tbuf[tx][ty * 4 + i];
        __nv_bfloat16 h, l;
        split_bf16(v, h, l);
        size_t off = (size_t)(nn0 + ty * 4 + i) * D_ + kk0 + tx;
        hi[off] = h;
        lo[off] = l;
    }
}

// =================================================================
// Split-bf16 GEMM via mma.sync. phase 0: q/k/v/Qr -> fp16 hi/lo head
// layout (q gets +cb). phase 1: oproj -> g_res (+Ev+Wo_b).
// =================================================================
#define KC 32
#define SROW 80
#define MAT_BYTES (128 * SROW)
#define STAGE_BYTES (4 * MAT_BYTES)
#define GEMM_SMEM (2 * STAGE_BYTES)

__global__ __launch_bounds__(256)
void mma_gemm_kernel(int phase, const float* __restrict__ Ev,
                     const float* __restrict__ Wo_b,
                     const float* __restrict__ cbv) {
    extern __shared__ __align__(16) char sm[];
    int tid = threadIdx.x;
    int lane = tid & 31, wid = tid >> 5;

    int t = blockIdx.x;
    const __nv_bfloat16 *Ahi, *Alo;
    int row0, col0, which;
    if (phase == 0) {
        if (t < 384) {
            which = t >> 7;
            int loc = t & 127;
            row0 = (loc >> 3) * 128;
            col0 = (loc & 7) * 128;
            if (which == 0) { Ahi = g_Ehi;  Alo = g_Elo;  }
            else            { Ahi = g_Evhi; Alo = g_Evlo; }
        } else {
            which = 3;
            int loc = t - 384;
            row0 = (loc >> 3) * 128;
            col0 = (loc & 7) * 128;
            Ahi = g_Rhi; Alo = g_Rlo;
        }
    } else {
        which = 4;
        row0 = (t >> 3) * 128;
        col0 = (t & 7) * 128;
        Ahi = g_Ohi; Alo = g_Olo;
    }
    const __nv_bfloat16* Bhi = g_WThi + (size_t)which * D_ * D_;
    const __nv_bfloat16* Blo = g_WTlo + (size_t)which * D_ * D_;

    const int wm = (wid >> 2) * 64;
    const int wn = (wid & 3) * 32;

    float c[4][4][4];
#pragma unroll
    for (int a = 0; a < 4; a++)
#pragma unroll
        for (int b = 0; b < 4; b++)
#pragma unroll
            for (int e = 0; e < 4; e++) c[a][b][e] = 0.f;

    uint4 pr[8];
    {
#pragma unroll
        for (int l = 0; l < 2; l++) {
            int idx = tid + 256 * l;
            int row = idx >> 2, colc = (idx & 3) * 8;
            size_t ga = (size_t)(row0 + row) * D_ + colc;
            size_t gb = (size_t)(col0 + row) * D_ + colc;
            pr[l * 4 + 0] = *(const uint4*)(Ahi + ga);
            pr[l * 4 + 1] = *(const uint4*)(Alo + ga);
            pr[l * 4 + 2] = *(const uint4*)(Bhi + gb);
            pr[l * 4 + 3] = *(const uint4*)(Blo + gb);
        }
        char* base = sm;
#pragma unroll
        for (int l = 0; l < 2; l++) {
            int idx = tid + 256 * l;
            int row = idx >> 2, colc = (idx & 3) * 8;
            int so = row * SROW + colc * 2;
            *(uint4*)(base + so)                 = pr[l * 4 + 0];
            *(uint4*)(base + MAT_BYTES + so)     = pr[l * 4 + 1];
            *(uint4*)(base + 2 * MAT_BYTES + so) = pr[l * 4 + 2];
            *(uint4*)(base + 3 * MAT_BYTES + so) = pr[l * 4 + 3];
        }
    }
    __syncthreads();

    for (int ch = 0; ch < D_ / KC; ch++) {
        if (ch + 1 < D_ / KC) {
            int kc0 = (ch + 1) * KC;
#pragma unroll
            for (int l = 0; l < 2; l++) {
                int idx = tid + 256 * l;
                int row = idx >> 2, colc = (idx & 3) * 8;
                size_t ga = (size_t)(row0 + row) * D_ + kc0 + colc;
                size_t gb = (size_t)(col0 + row) * D_ + kc0 + colc;
                pr[l * 4 + 0] = *(const uint4*)(Ahi + ga);
                pr[l * 4 + 1] = *(const uint4*)(Alo + ga);
                pr[l * 4 + 2] = *(const uint4*)(Bhi + gb);
                pr[l * 4 + 3] = *(const uint4*)(Blo + gb);
            }
        }
        {
            const char* base = sm + (ch & 1) * STAGE_BYTES;
#pragma unroll
            for (int ks = 0; ks < 2; ks++) {
                int kb = ks * 32;
                unsigned bh[4][2], bl[4][2];
#pragma unroll
                for (int nt = 0; nt < 4; nt++) {
                    const char* bp = base + 2 * MAT_BYTES +
                        (wn + nt * 8 + (lane >> 2)) * SROW + kb + (lane & 3) * 4;
                    bh[nt][0] = *(const unsigned*)bp;
                    bh[nt][1] = *(const unsigned*)(bp + 16);
                    bl[nt][0] = *(const unsigned*)(bp + MAT_BYTES);
                    bl[nt][1] = *(const unsigned*)(bp + MAT_BYTES + 16);
                }
#pragma unroll
                for (int mt = 0; mt < 4; mt++) {
                    const char* ap = base +
                        (wm + mt * 16 + (lane >> 2)) * SROW + kb + (lane & 3) * 4;
                    unsigned a0 = *(const unsigned*)ap;
                    unsigned a1 = *(const unsigned*)(ap + 8 * SROW);
                    unsigned a2 = *(const unsigned*)(ap + 16);
                    unsigned a3 = *(const unsigned*)(ap + 8 * SROW + 16);
                    unsigned l0 = *(const unsigned*)(ap + MAT_BYTES);
                    unsigned l1 = *(const unsigned*)(ap + MAT_BYTES + 8 * SROW);
                    unsigned l2 = *(const unsigned*)(ap + MAT_BYTES + 16);
                    unsigned l3 = *(const unsigned*)(ap + MAT_BYTES + 8 * SROW + 16);
#pragma unroll
                    for (int nt = 0; nt < 4; nt++) {
                        mma_bf16(c[mt][nt], a0, a1, a2, a3, bh[nt][0], bh[nt][1]);
                        mma_bf16(c[mt][nt], l0, l1, l2, l3, bh[nt][0], bh[nt][1]);
                        mma_bf16(c[mt][nt], a0, a1, a2, a3, bl[nt][0], bl[nt][1]);
                    }
                }
            }
        }
        if (ch + 1 < D_ / KC) {
            char* base = sm + ((ch + 1) & 1) * STAGE_BYTES;
#pragma unroll
            for (int l = 0; l < 2; l++) {
                int idx = tid + 256 * l;
                int row = idx >> 2, colc = (idx & 3) * 8;
                int so = row * SROW + colc * 2;
                *(uint4*)(base + so)                 = pr[l * 4 + 0];
                *(uint4*)(base + MAT_BYTES + so)     = pr[l * 4 + 1];
                *(uint4*)(base + 2 * MAT_BYTES + so) = pr[l * 4 + 2];
                *(uint4*)(base + 3 * MAT_BYTES + so) = pr[l * 4 + 3];
            }
        }
        __syncthreads();
    }

    // ---- epilogue ----
#pragma unroll
    for (int mt = 0; mt < 4; mt++) {
#pragma unroll
        for (int nt = 0; nt < 4; nt++) {
            int r   = row0 + wm + mt * 16 + (lane >> 2);
            int col = col0 + wn + nt * 8 + (lane & 3) * 2;
            if (phase == 0) {
                float v00 = c[mt][nt][0], v01 = c[mt][nt][1];
                float v10 = c[mt][nt][2], v11 = c[mt][nt][3];
                if (which == 0) {
                    float cb0 = cbv[col], cb1 = cbv[col + 1];
                    v00 += cb0; v01 += cb1; v10 += cb0; v11 += cb1;
                }
                int hh = col >> 6, d = col & 63;
                __half *dh, *dl;
                size_t off0, off1;
                if (which == 3) {
                    dh = g_Qrh; dl = g_Qrl;
                    off0 = ((size_t)(hh * L_ + r)) * DH + d;
                    off1 = ((size_t)(hh * L_ + r + 8)) * DH + d;
                } else {
                    dh = (which == 0) ? g_qch : (which == 1) ? g_kh : g_vh;
                    dl = (which == 0) ? g_qcl : (which == 1) ? g_kl : g_vl;
                    int bb = r >> 10, ir = r & 1023;
                    off0 = ((size_t)((bb * H_ + hh) * L_ + ir)) * DH + d;
                    off1 = off0 + 8 * DH;
                }
                __half h00 = __float2half(v00), h01 = __float2half(v01);
                __half h10 = __float2half(v10), h11 = __float2half(v11);
                __half l00 = __float2half(v00 - __half2float(h00));
                __half l01 = __float2half(v01 - __half2float(h01));
                __half l10 = __float2half(v10 - __half2float(h10));
                __half l11 = __float2half(v11 - __half2float(h11));
                __half2 p;
                p.x = h00; p.y = h01; *(__half2*)(dh + off0) = p;
                p.x = l00; p.y = l01; *(__half2*)(dl + off0) = p;
                p.x = h10; p.y = h11; *(__half2*)(dh + off1) = p;
                p.x = l10; p.y = l11; *(__half2*)(dl + off1) = p;
            } else {
                float2 wb = *(const float2*)(Wo_b + col);
                float2 e0 = *(const float2*)(Ev + (size_t)r * D_ + col);
                float2 e1 = *(const float2*)(Ev + (size_t)(r + 8) * D_ + col);
                float2 o0 = make_float2(c[mt][nt][0] + wb.x + e0.x, c[mt][nt][1] + wb.y + e0.y);
                float2 o1 = make_float2(c[mt][nt][2] + wb.x + e1.x, c[mt][nt][3] + wb.y + e1.y);
                *(float2*)(g_res + (size_t)r * D_ + col) = o0;
                *(float2*)(g_res + (size_t)(r + 8) * D_ + col) = o1;
            }
        }
    }
}

// =================================================================
// mma attention, 256 threads = 2 groups x 4 warps. Group g owns
// j-columns [32g, 32g+32) of every tile; independent online softmax
// per group; split-softmax merge at the end. Band GEMM splits by
// t-half = group. Epilogue writes bf16 hi/lo row-major directly.
// =================================================================
#define HSTRIDE 72                      // halves per smem row (144 B)
#define T64  (64 * HSTRIDE * 2)         // 9216 B
#define T128 (128 * HSTRIDE * 2)        // 18432 B
#define OFF_QCH 0
#define OFF_QCL (OFF_QCH + T64)
#define OFF_KH  (OFF_QCL + T64)
#define OFF_KL  (OFF_KH + T64)
#define OFF_VH  (OFF_KL + T64)
#define OFF_VL  (OFF_VH + T64)
#define OFF_QRH (OFF_VL + T64)
#define OFF_QRL (OFF_QRH + T128)
#define OFF_SPOS (OFF_QRL + T128)       // float [64][65]; reused as O1 buffer
#define OFF_R    (OFF_SPOS + 64 * 65 * 4)  // float[128]; reused as m/l buffer
#define OFF_DELTA (OFF_R + 128 * 4)
#define ATTN_SMEM (OFF_DELTA + 64 * 4)

__global__ __launch_bounds__(256, 2)
void attn_mma_kernel(const float* __restrict__ cbv, const float* __restrict__ pbv) {
    extern __shared__ __align__(16) char sm[];
    unsigned sbase = smem_u32(sm);
    int tid = threadIdx.x, lane = tid & 31, w = tid >> 5;
    int grp = w >> 2, wq = w & 3;
    int ib = blockIdx.x, bh = blockIdx.y, h = bh & 15;
    int i0 = ib * 64;
    const int jbase = grp * 32;

    const __half* qch_g = g_qch + (size_t)bh * L_ * DH;
    const __half* qcl_g = g_qcl + (size_t)bh * L_ * DH;
    const __half* kh_g  = g_kh  + (size_t)bh * L_ * DH;
    const __half* kl_g  = g_kl  + (size_t)bh * L_ * DH;
    const __half* vh_g  = g_vh  + (size_t)bh * L_ * DH;
    const __half* vl_g  = g_vl  + (size_t)bh * L_ * DH;
    const __half* Qrh_g = g_Qrh + (size_t)h * L_ * DH;
    const __half* Qrl_g = g_Qrl + (size_t)h * L_ * DH;

    float* Spos  = (float*)(sm + OFF_SPOS);
    float* r_s   = (float*)(sm + OFF_R);
    float* delta = (float*)(sm + OFF_DELTA);

    if (tid < 64) delta[tid] = pbv[h * DH + tid] - cbv[h * DH + tid];

    // load qc tile (64 x 64 hi/lo)
#pragma unroll
    for (int it = 0; it < 2; it++) {
        int idx = tid + 256 * it;
        int row = idx >> 3, dc = (idx & 7) * 8;
        size_t go = (size_t)(i0 + row) * DH + dc;
        *(uint4*)(sm + OFF_QCH + row * 144 + dc * 2) = *(const uint4*)(qch_g + go);
        *(uint4*)(sm + OFF_QCL + row * 144 + dc * 2) = *(const uint4*)(qcl_g + go);
    }
    __syncthreads();

    float O[8][4];
#pragma unroll
    for (int dn = 0; dn < 8; dn++)
#pragma unroll
        for (int e = 0; e < 4; e++) O[dn][e] = 0.f;
    float m_a = -1e30f, m_b = -1e30f, l_a = 0.f, l_b = 0.f;
    const int ra = lane >> 2;                 // 0..7
    const int il_a = 16 * wq + ra, il_b = il_a + 8;

    for (int jt = 0; jt < 16; jt++) {
        int j0 = jt * 64;
        bool pos = (jt <= ib);
        __syncthreads();
        // load k, v hi/lo (256 threads)
#pragma unroll
        for (int it = 0; it < 2; it++) {
            int idx = tid + 256 * it;
            int row = idx >> 3, dc = (idx & 7) * 8;
            size_t go = (size_t)(j0 + row) * DH + dc;
            int so = row * 144 + dc * 2;
            *(uint4*)(sm + OFF_KH + so) = *(const uint4*)(kh_g + go);
            *(uint4*)(sm + OFF_KL + so) = *(const uint4*)(kl_g + go);
            *(uint4*)(sm + OFF_VH + so) = *(const uint4*)(vh_g + go);
            *(uint4*)(sm + OFF_VL + so) = *(const uint4*)(vl_g + go);
        }
        int c0 = L_ - 64 - i0 + j0;
        if (pos) {
#pragma unroll
            for (int it = 0; it < 4; it++) {
                int idx = tid + 256 * it;
                int row = idx >> 3, dc = (idx & 7) * 8;
                int m = c0 + row;
                uint4 zh = make_uint4(0, 0, 0, 0), zl = make_uint4(0, 0, 0, 0);
                if (m < L_) {
                    size_t go = (size_t)m * DH + dc;
                    zh = *(const uint4*)(Qrh_g + go);
                    zl = *(const uint4*)(Qrl_g + go);
                }
                int so = row * 144 + dc * 2;
                *(uint4*)(sm + OFF_QRH + so) = zh;
                *(uint4*)(sm + OFF_QRL + so) = zl;
            }
        }
        __syncthreads();
        if (pos) {
            // r[t] = delta . Qr[t], t = 0..127 (threads 0..127)
            if (tid < 128) {
                const __half* qh = (const __half*)(sm + OFF_QRH) + tid * HSTRIDE;
                const __half* ql = (const __half*)(sm + OFF_QRL) + tid * HSTRIDE;
                float acc = 0.f;
#pragma unroll 16
                for (int d = 0; d < 64; d++)
                    acc += delta[d] * (__half2float(qh[d]) + __half2float(ql[d]));
                r_s[tid] = acc;
            }
            __syncthreads();

            // band GEMM for this group's t-half, scatter pre-shifted into Spos
            float g[8][4];
#pragma unroll
            for (int tn = 0; tn < 8; tn++)
#pragma unroll
                for (int e = 0; e < 4; e++) g[tn][e] = 0.f;
#pragma unroll
            for (int kk = 0; kk < 4; kk++) {
                unsigned aqh[4], aql[4];
                unsigned ao = ((16 * wq + (lane & 15)) * HSTRIDE + kk * 16 + (lane >> 4) * 8) * 2;
                ldsm_x4(aqh[0], aqh[1], aqh[2], aqh[3], sbase + OFF_QCH + ao);
                ldsm_x4(aql[0], aql[1], aql[2], aql[3], sbase + OFF_QCL + ao);
#pragma unroll
                for (int tp = 0; tp < 4; tp++) {
                    unsigned b0, b1, b2, b3;
                    unsigned bo = (((grp * 8 + 2 * tp + (lane >> 4)) * 8 + (lane & 7)) * HSTRIDE
                                   + kk * 16 + ((lane >> 3) & 1) * 8) * 2;
                    ldsm_x4(b0, b1, b2, b3, sbase + OFF_QRH + bo);
                    mma_f16(g[2 * tp],     aqh[0], aqh[1], aqh[2], aqh[3], b0, b1);
                    mma_f16(g[2 * tp + 1], aqh[0], aqh[1], aqh[2], aqh[3], b2, b3);
                    mma_f16(g[2 * tp],     aql[0], aql[1], aql[2], aql[3], b0, b1);
                    mma_f16(g[2 * tp + 1], aql[0], aql[1], aql[2], aql[3], b2, b3);
                    ldsm_x4(b0, b1, b2, b3, sbase + OFF_QRL + bo);
                    mma_f16(g[2 * tp],     aqh[0], aqh[1], aqh[2], aqh[3], b0, b1);
                    mma_f16(g[2 * tp + 1], aqh[0], aqh[1], aqh[2], aqh[3], b2, b3);
                }
            }
#pragma unroll
            for (int tn = 0; tn < 8; tn++) {
                int tbase = grp * 64 + tn * 8 + (lane & 3) * 2;
#pragma unroll
                for (int e = 0; e < 2; e++) {
                    int tt = tbase + e;
                    float rv = r_s[tt];
                    int ja = tt + il_a - 63;
                    if (ja >= 0 && ja < 64) Spos[il_a * 65 + ja] = g[tn][e] + rv;
                    int jb = tt + il_b - 63;
                    if (jb >= 0 && jb < 64) Spos[il_b * 65 + jb] = g[tn][2 + e] + rv;
                }
            }
        }

        // content scores for this group's 32 j-columns
        float s[4][4];
#pragma unroll
        for (int jn = 0; jn < 4; jn++)
#pragma unroll
            for (int e = 0; e < 4; e++) s[jn][e] = 0.f;
#pragma unroll
        for (int kk = 0; kk < 4; kk++) {
            unsigned aqh[4], aql[4];
            unsigned ao = ((16 * wq + (lane & 15)) * HSTRIDE + kk * 16 + (lane >> 4) * 8) * 2;
            ldsm_x4(aqh[0], aqh[1], aqh[2], aqh[3], sbase + OFF_QCH + ao);
            ldsm_x4(aql[0], aql[1], aql[2], aql[3], sbase + OFF_QCL + ao);
#pragma unroll
            for (int jp = 0; jp < 2; jp++) {
                unsigned b0, b1, b2, b3;
                unsigned bo = (((jbase >> 3) * 8 * HSTRIDE) +
                               (((2 * jp + (lane >> 4)) * 8 + (lane & 7)) * HSTRIDE)
                               + kk * 16 + ((lane >> 3) & 1) * 8) * 2;
                ldsm_x4(b0, b1, b2, b3, sbase + OFF_KH + bo);
                mma_f16(s[2 * jp],     aqh[0], aqh[1], aqh[2], aqh[3], b0, b1);
                mma_f16(s[2 * jp + 1], aqh[0], aqh[1], aqh[2], aqh[3], b2, b3);
                mma_f16(s[2 * jp],     aql[0], aql[1], aql[2], aql[3], b0, b1);
                mma_f16(s[2 * jp + 1], aql[0], aql[1], aql[2], aql[3], b2, b3);
                ldsm_x4(b0, b1, b2, b3, sbase + OFF_KL + bo);
                mma_f16(s[2 * jp],     aqh[0], aqh[1], aqh[2], aqh[3], b0, b1);
                mma_f16(s[2 * jp + 1], aqh[0], aqh[1], aqh[2], aqh[3], b2, b3);
            }
        }
        if (pos) {
            __syncthreads();   // all groups' Spos scatters visible
#pragma unroll
            for (int jn = 0; jn < 4; jn++) {
                int jc = jbase + jn * 8 + (lane & 3) * 2;
                s[jn][0] += Spos[il_a * 65 + jc];
                s[jn][1] += Spos[il_a * 65 + jc + 1];
                s[jn][2] += Spos[il_b * 65 + jc];
                s[jn][3] += Spos[il_b * 65 + jc + 1];
            }
        }

        // online softmax (warp-local, group's column subset)
        float mta = -1e30f, mtb = -1e30f;
#pragma unroll
        for (int jn = 0; jn < 4; jn++) {
            mta = fmaxf(mta, fmaxf(s[jn][0], s[jn][1]));
            mtb = fmaxf(mtb, fmaxf(s[jn][2], s[jn][3]));
        }
        mta = fmaxf(mta, __shfl_xor_sync(0xffffffffu, mta, 1));
        mta = fmaxf(mta, __shfl_xor_sync(0xffffffffu, mta, 2));
        mtb = fmaxf(mtb, __shfl_xor_sync(0xffffffffu, mtb, 1));
        mtb = fmaxf(mtb, __shfl_xor_sync(0xffffffffu, mtb, 2));
        float mna = fmaxf(m_a, mta), mnb = fmaxf(m_b, mtb);
        float sca = __expf(m_a - mna), scb = __expf(m_b - mnb);
        m_a = mna; m_b = mnb;
        float suma = 0.f, sumb = 0.f;
#pragma unroll
        for (int jn = 0; jn < 4; jn++) {
            s[jn][0] = __expf(s[jn][0] - mna);
            s[jn][1] = __expf(s[jn][1] - mna);
            s[jn][2] = __expf(s[jn][2] - mnb);
            s[jn][3] = __expf(s[jn][3] - mnb);
            suma += s[jn][0] + s[jn][1];
            sumb += s[jn][2] + s[jn][3];
        }
        suma += __shfl_xor_sync(0xffffffffu, suma, 1);
        suma += __shfl_xor_sync(0xffffffffu, suma, 2);
        sumb += __shfl_xor_sync(0xffffffffu, sumb, 1);
        sumb += __shfl_xor_sync(0xffffffffu, sumb, 2);
        l_a = l_a * sca + suma;
        l_b = l_b * scb + sumb;
#pragma unroll
        for (int dn = 0; dn < 8; dn++) {
            O[dn][0] *= sca; O[dn][1] *= sca;
            O[dn][2] *= scb; O[dn][3] *= scb;
        }

        // O += P @ V  (k-dim = group's 32 j rows)
#pragma unroll
        for (int kj = 0; kj < 2; kj++) {
            __half h00 = __float2half(s[2 * kj][0]),     h01 = __float2half(s[2 * kj][1]);
            __half h02 = __float2half(s[2 * kj][2]),     h03 = __float2half(s[2 * kj][3]);
            __half h10 = __float2half(s[2 * kj + 1][0]), h11 = __float2half(s[2 * kj + 1][1]);
            __half h12 = __float2half(s[2 * kj + 1][2]), h13 = __float2half(s[2 * kj + 1][3]);
            unsigned pa0 = pack_h2(h00, h01), pa1 = pack_h2(h02, h03);
            unsigned pa2 = pack_h2(h10, h11), pa3 = pack_h2(h12, h13);
            unsigned pl0 = pack_h2(__float2half(s[2 * kj][0] - __half2float(h00)),
                                   __float2half(s[2 * kj][1] - __half2float(h01)));
            unsigned pl1 = pack_h2(__float2half(s[2 * kj][2] - __half2float(h02)),
                                   __float2half(s[2 * kj][3] - __half2float(h03)));
            unsigned pl2 = pack_h2(__float2half(s[2 * kj + 1][0] - __half2float(h10)),
                                   __float2half(s[2 * kj + 1][1] - __half2float(h11)));
            unsigned pl3 = pack_h2(__float2half(s[2 * kj + 1][2] - __half2float(h12)),
                                   __float2half(s[2 * kj + 1][3] - __half2float(h13)));
#pragma unroll
            for (int dp = 0; dp < 4; dp++) {
                unsigned v0, v1, v2, v3;
                unsigned bo = ((jbase + kj * 16 + ((lane >> 3) & 1) * 8 + (lane & 7)) * HSTRIDE
                               + (2 * dp + (lane >> 4)) * 8) * 2;
                ldsm_x4_t(v0, v1, v2, v3, sbase + OFF_VH + bo);
                mma_f16(O[2 * dp],     pa0, pa1, pa2, pa3, v0, v1);
                mma_f16(O[2 * dp + 1], pa0, pa1, pa2, pa3, v2, v3);
                mma_f16(O[2 * dp],     pl0, pl1, pl2, pl3, v0, v1);
                mma_f16(O[2 * dp + 1], pl0, pl1, pl2, pl3, v2, v3);
                ldsm_x4_t(v0, v1, v2, v3, sbase + OFF_VL + bo);
                mma_f16(O[2 * dp],     pa0, pa1, pa2, pa3, v0, v1);
                mma_f16(O[2 * dp + 1], pa0, pa1, pa2, pa3, v2, v3);
            }
        }
    }

    // ---- combine the two groups (split-softmax merge) + store ----
    __syncthreads();
    if (grp == 1) {
#pragma unroll
        for (int dn = 0; dn < 8; dn++) {
            int d = dn * 8 + (lane & 3) * 2;
            Spos[il_a * 65 + d]     = O[dn][0];
            Spos[il_a * 65 + d + 1] = O[dn][1];
            Spos[il_b * 65 + d]     = O[dn][2];
            Spos[il_b * 65 + d + 1] = O[dn][3];
        }
        if ((lane & 3) == 0) {
            r_s[il_a] = m_a; r_s[64 + il_a] = l_a;
            r_s[il_b] = m_b; r_s[64 + il_b] = l_b;
        }
    }
    __syncthreads();
    if (grp == 0) {
        float m1a = r_s[il_a], l1a = r_s[64 + il_a];
        float m1b = r_s[il_b], l1b = r_s[64 + il_b];
        float ma = fmaxf(m_a, m1a), mb = fmaxf(m_b, m1b);
        float w0a = __expf(m_a - ma), w1a = __expf(m1a - ma);
        float w0b = __expf(m_b - mb), w1b = __expf(m1b - mb);
        float inva = 1.f / (l_a * w0a + l1a * w1a);
        float invb = 1.f / (l_b * w0b + l1b * w1b);
        int bb = bh >> 4, hh = bh & 15;
        size_t ro_a = ((size_t)(bb * 1024 + i0 + il_a)) * D_ + hh * 64;
        size_t ro_b = ((size_t)(bb * 1024 + i0 + il_b)) * D_ + hh * 64;
#pragma unroll
        for (int dn = 0; dn < 8; dn++) {
            int d = dn * 8 + (lane & 3) * 2;
            float va0 = (O[dn][0] * w0a + Spos[il_a * 65 + d]     * w1a) * inva;
            float va1 = (O[dn][1] * w0a + Spos[il_a * 65 + d + 1] * w1a) * inva;
            float vb0 = (O[dn][2] * w0b + Spos[il_b * 65 + d]     * w1b) * invb;
            float vb1 = (O[dn][3] * w0b + Spos[il_b * 65 + d + 1] * w1b) * invb;
            __nv_bfloat16 h0, l0, h1, l1;
            split_bf16(va0, h0, l0); split_bf16(va1, h1, l1);
            __nv_bfloat162 ph; ph.x = h0; ph.y = h1;
            __nv_bfloat162 pl; pl.x = l0; pl.y = l1;
            *(__nv_bfloat162*)(g_Ohi + ro_a + d) = ph;
            *(__nv_bfloat162*)(g_Olo + ro_a + d) = pl;
            split_bf16(vb0, h0, l0); split_bf16(vb1, h1, l1);
            ph.x = h0; ph.y = h1; pl.x = l0; pl.y = l1;
            *(__nv_bfloat162*)(g_Ohi + ro_b + d) = ph;
            *(__nv_bfloat162*)(g_Olo + ro_b + d) = pl;
        }
    }
}

// =================================================================
// LayerNorm (unchanged).
// =================================================================
__global__ __launch_bounds__(256)
void ln_kernel(const float* __restrict__ gamma,
               const float* __restrict__ beta,
               float* __restrict__ out) {
    int row = blockIdx.x;
    int tid = threadIdx.x;
    const float* x = g_res + (size_t)row * D_;
    float4 v = *(const float4*)(x + tid * 4);
    float s  = v.x + v.y + v.z + v.w;
    float ss = v.x * v.x + v.y * v.y + v.z * v.z + v.w * v.w;
#pragma unroll
    for (int off = 16; off > 0; off >>= 1) {
        s  += __shfl_down_sync(0xffffffffu, s,  off);
        ss += __shfl_down_sync(0xffffffffu, ss, off);
    }
    __shared__ float sbuf[8], ssbuf[8];
    __shared__ float mu_s, inv_s;
    int w = tid >> 5;
    if ((tid & 31) == 0) { sbuf[w] = s; ssbuf[w] = ss; }
    __syncthreads();
    if (tid == 0) {
        float st = 0.f, sst = 0.f;
#pragma unroll
        for (int i = 0; i < 8; i++) { st += sbuf[i]; sst += ssbuf[i]; }
        float mu = st * (1.0f / D_);
        float var = sst * (1.0f / D_) - mu * mu;
        mu_s = mu;
        inv_s = rsqrtf(var + 1e-5f);
    }
    __syncthreads();
    float mu = mu_s, inv = inv_s;
    float4 g4 = *(const float4*)(gamma + tid * 4);
    float4 b4 = *(const float4*)(beta + tid * 4);
    float4 o4;
    o4.x = (v.x - mu) * inv * g4.x + b4.x;
    o4.y = (v.y - mu) * inv * g4.y + b4.y;
    o4.z = (v.z - mu) * inv * g4.z + b4.z;
    o4.w = (v.w - mu) * inv * g4.w + b4.w;
    *(float4*)(out + (size_t)row * D_ + tid * 4) = o4;
}

// =================================================================
extern "C" void kernel_launch(void* const* d_in, const int* in_sizes, int n_in,
                              void* d_out, int out_size) {
    const float* E    = (const float*)d_in[0];
    const float* Ev   = (const float*)d_in[1];
    const float* R    = (const float*)d_in[2];
    const float* Wq   = (const float*)d_in[3];
    const float* Wke  = (const float*)d_in[4];
    const float* Wkr  = (const float*)d_in[5];
    const float* Wv   = (const float*)d_in[6];
    const float* cb   = (const float*)d_in[7];
    const float* pb   = (const float*)d_in[8];
    const float* Wo_w = (const float*)d_in[9];
    const float* Wo_b = (const float*)d_in[10];
    const float* ln_g = (const float*)d_in[11];
    const float* ln_b = (const float*)d_in[12];
    float* out = (float*)d_out;

    cudaFuncSetAttribute(mma_gemm_kernel, cudaFuncAttributeMaxDynamicSharedMemorySize,
                         GEMM_SMEM);
    cudaFuncSetAttribute(attn_mma_kernel, cudaFuncAttributeMaxDynamicSharedMemorySize,
                         ATTN_SMEM);

    dim3 sg(B_ * L_ * D_ / 4 / 256, 1, 3);
    split_convert_kernel<<<sg, 256>>>(E, Ev, R);
    dim3 wg(D_ / 32, D_ / 32, 5);
    wt_convert_kernel<<<wg, 256>>>(Wq, Wke, Wv, Wkr, Wo_w);

    mma_gemm_kernel<<<448, 256, GEMM_SMEM>>>(0, Ev, Wo_b, cb);

    dim3 ag(L_ / 64, B_ * H_);
    attn_mma_kernel<<<ag, 256, ATTN_SMEM>>>(cb, pb);

    mma_gemm_kernel<<<128, 256, GEMM_SMEM>>>(1, Ev, Wo_b, cb);

    ln_kernel<<<B_ * L_, 256>>>(ln_g, ln_b, out);
}